// round 12
// baseline (speedup 1.0000x reference)
#include <cuda_runtime.h>
#include <cuda_bf16.h>
#include <cstdint>

#define NNi   1024
#define BBi   8
#define TTi   40
#define DINi  16
#define ROWSi 8192
#define DT_SUB 0.025f

typedef __nv_bfloat16 bf16;

// ------------------- static scratch (no runtime allocation) -------------------
__device__ float g_obs[(size_t)BBi*TTi*NNi];
__device__ float g_S  [(size_t)ROWSi*128];
__device__ float g_u  [(size_t)ROWSi*128];
__device__ float g_pre[(size_t)TTi*ROWSi*128];
// bf16 split operand twins
__device__ bf16 g_Ahi  [(size_t)BBi*NNi*NNi];
__device__ bf16 g_Alo  [(size_t)BBi*NNi*NNi];
__device__ bf16 g_A2hi [(size_t)BBi*NNi*NNi];
__device__ bf16 g_A2lo [(size_t)BBi*NNi*NNi];
__device__ bf16 g_Shi  [(size_t)ROWSi*128];
__device__ bf16 g_Slo  [(size_t)ROWSi*128];
__device__ bf16 g_RHhi [(size_t)ROWSi*128];
__device__ bf16 g_RHlo [(size_t)ROWSi*128];
__device__ bf16 g_B1hi [(size_t)ROWSi*128];
__device__ bf16 g_B1lo [(size_t)ROWSi*128];
__device__ bf16 g_B2hi [(size_t)ROWSi*128];
__device__ bf16 g_B2lo [(size_t)ROWSi*128];
__device__ bf16 g_Xhi  [(size_t)BBi*TTi*NNi*DINi];
__device__ bf16 g_Xlo  [(size_t)BBi*TTi*NNi*DINi];
__device__ bf16 g_AX1hi[(size_t)BBi*TTi*NNi*DINi];
__device__ bf16 g_AX1lo[(size_t)BBi*TTi*NNi*DINi];
__device__ bf16 g_AX2hi[(size_t)BBi*TTi*NNi*DINi];
__device__ bf16 g_AX2lo[(size_t)BBi*TTi*NNi*DINi];
__device__ bf16 g_preZhi[(size_t)39*ROWSi*64];
__device__ bf16 g_preZlo[(size_t)39*ROWSi*64];
__device__ bf16 g_T1hi [(size_t)39*ROWSi*64];
__device__ bf16 g_T1lo [(size_t)39*ROWSi*64];
__device__ bf16 g_T2hi [(size_t)39*ROWSi*64];
__device__ bf16 g_T2lo [(size_t)39*ROWSi*64];
__device__ bf16 g_zero_bf[16];
// padded bf16 weight splits
__device__ bf16 g_oW0hi  [2*192*64];
__device__ bf16 g_oW0lo  [2*192*64];
__device__ bf16 g_oWouthi[2*64*64];
__device__ bf16 g_oWoutlo[2*64*64];
__device__ bf16 g_gWghi  [2*256*128];
__device__ bf16 g_gWglo  [2*256*128];
__device__ bf16 g_gWchi  [2*256*64];
__device__ bf16 g_gWclo  [2*256*64];
__device__ bf16 g_hWhi   [4*64*64];
__device__ bf16 g_hWlo   [4*64*64];

// ------------------- asm helpers -------------------
__device__ __forceinline__ uint32_t smem_u32(const void* p) {
    uint32_t a;
    asm("{ .reg .u64 t; cvta.to.shared.u64 t, %1; cvt.u32.u64 %0, t; }" : "=r"(a) : "l"(p));
    return a;
}
__device__ __forceinline__ void ldm4(uint32_t* r, uint32_t a) {
    asm volatile("ldmatrix.sync.aligned.m8n8.x4.shared.b16 {%0,%1,%2,%3}, [%4];"
        : "=r"(r[0]), "=r"(r[1]), "=r"(r[2]), "=r"(r[3]) : "r"(a));
}
__device__ __forceinline__ void ldm4t(uint32_t* r, uint32_t a) {
    asm volatile("ldmatrix.sync.aligned.m8n8.x4.trans.shared.b16 {%0,%1,%2,%3}, [%4];"
        : "=r"(r[0]), "=r"(r[1]), "=r"(r[2]), "=r"(r[3]) : "r"(a));
}
__device__ __forceinline__ void mma_bf(float* c, const uint32_t* a, uint32_t b0, uint32_t b1) {
    asm volatile("mma.sync.aligned.m16n8k16.row.col.f32.bf16.bf16.f32 "
        "{%0,%1,%2,%3}, {%4,%5,%6,%7}, {%8,%9}, {%0,%1,%2,%3};"
        : "+f"(c[0]), "+f"(c[1]), "+f"(c[2]), "+f"(c[3])
        : "r"(a[0]), "r"(a[1]), "r"(a[2]), "r"(a[3]), "r"(b0), "r"(b1));
}
__device__ __forceinline__ void cpa16(uint32_t sm, const void* gm) {
    asm volatile("cp.async.cg.shared.global [%0], [%1], 16;"
        :: "r"(sm), "l"(__cvta_generic_to_global(gm)));
}
#define CP_COMMIT() asm volatile("cp.async.commit_group;" ::: "memory")
#define CP_WAIT0()  asm volatile("cp.async.wait_group 0;" ::: "memory")
#define CP_WAIT1()  asm volatile("cp.async.wait_group 1;" ::: "memory")

__device__ __forceinline__ void split_bf(float v, bf16& h, bf16& l) {
    h = __float2bfloat16_rn(v);
    l = __float2bfloat16_rn(v - __bfloat162float(h));
}

// ------------------- init / split kernels -------------------
__global__ void initX_k(const float4* __restrict__ v, const float4* __restrict__ m) {
    int i = blockIdx.x * 256 + threadIdx.x;
    float s = 0.f;
#pragma unroll
    for (int q = 0; q < 4; q++) {
        float4 vv = v[i * 4 + q], mm = m[i * 4 + q];
        s += fabsf(mm.x) + fabsf(mm.y) + fabsf(mm.z) + fabsf(mm.w);
        float4 x = make_float4(vv.x * mm.x, vv.y * mm.y, vv.z * mm.z, vv.w * mm.w);
        size_t o = (size_t)i * 16 + q * 4;
        split_bf(x.x, g_Xhi[o + 0], g_Xlo[o + 0]);
        split_bf(x.y, g_Xhi[o + 1], g_Xlo[o + 1]);
        split_bf(x.z, g_Xhi[o + 2], g_Xlo[o + 2]);
        split_bf(x.w, g_Xhi[o + 3], g_Xlo[o + 3]);
    }
    g_obs[i] = (s > 1e-4f) ? 1.f : 0.f;
}
__global__ void initS_k(const float* __restrict__ h0, const float* __restrict__ z0) {
    int i = blockIdx.x * 256 + threadIdx.x;
    int c = i & 127;
    float v = (c < 64) ? h0[c] : z0[c - 64];
    g_S[i] = v;
    split_bf(v, g_Shi[i], g_Slo[i]);
}
__global__ void splitA_k(const float* __restrict__ src, bf16* __restrict__ hi, bf16* __restrict__ lo) {
    size_t i = (size_t)blockIdx.x * 256 + threadIdx.x;
    split_bf(src[i], hi[i], lo[i]);
}
__global__ void splitW_k(const float* __restrict__ src, bf16* __restrict__ hi, bf16* __restrict__ lo,
                         int K, int N, int Npad) {
    int i = blockIdx.x * 256 + threadIdx.x;
    int k = i / Npad, n = i - k * Npad;
    float v = (k < K && n < N) ? src[k * N + n] : 0.f;
    split_bf(v, hi[i], lo[i]);
}

// ------------------- diffusion GEMM (64x128 tile, K=1024, 3-stage) -------------------
#define GP_STAGE  27648
#define A_LO_OFF  5120
#define B_OFF     10240
#define B_LO_OFF  8704

__device__ __forceinline__ void gp_load(
    uint32_t so, int k0, int row0, int col0, int bT,
    const bf16* __restrict__ Ah, const bf16* __restrict__ Al,
    const bf16* __restrict__ Bh, const bf16* __restrict__ Bl,
    int ldb, int bxmode)
{
    int t = threadIdx.x;
#pragma unroll
    for (int i = 0; i < 2; i++) {
        int c = t + i * 256;
        int arr = c >> 8, cc = c & 255, row = cc >> 2, seg = cc & 3;
        const bf16* g = (arr ? Al : Ah) + (size_t)(row0 + row) * NNi + k0 + seg * 8;
        cpa16(so + arr * A_LO_OFF + row * 80 + seg * 16, g);
    }
#pragma unroll
    for (int i = 0; i < 4; i++) {
        int c = t + i * 256;
        int arr = c >> 9, cc = c & 511, k = cc >> 4, seg = cc & 15;
        size_t off;
        if (bxmode) {
            int col = col0 + seg * 8;
            off = ((size_t)(bT + (col >> 4)) * NNi + (k0 + k)) * 16 + (col & 15);
        } else {
            off = (size_t)(k0 + k) * ldb + col0 + seg * 8;
        }
        cpa16(so + B_OFF + arr * B_LO_OFF + k * 272 + seg * 16, (arr ? Bl : Bh) + off);
    }
    CP_COMMIT();
}

__global__ void __launch_bounds__(256, 2) gemmP_hmma(
    const bf16* __restrict__ Ahi1, const bf16* __restrict__ Alo1,
    const bf16* __restrict__ Ahi2, const bf16* __restrict__ Alo2,
    const bf16* __restrict__ Bhi, const bf16* __restrict__ Blo,
    int ldb, size_t bstride, int bxmode,
    bf16* __restrict__ O1hi, bf16* __restrict__ O1lo,
    bf16* __restrict__ O2hi, bf16* __restrict__ O2lo,
    int ldo, size_t ostride, int oxmode)
{
    extern __shared__ char smraw[];
    int bz = blockIdx.z;
    int b = bz & 7, hop = bz >> 3;
    const bf16* Ah = (hop ? Ahi2 : Ahi1) + (size_t)b * NNi * NNi;
    const bf16* Al = (hop ? Alo2 : Alo1) + (size_t)b * NNi * NNi;
    const bf16* Bh = bxmode ? Bhi : Bhi + (size_t)b * bstride;
    const bf16* Bl = bxmode ? Blo : Blo + (size_t)b * bstride;
    bf16* Ohi = (hop ? O2hi : O1hi) + (oxmode ? 0 : (size_t)b * ostride);
    bf16* Olo = (hop ? O2lo : O1lo) + (oxmode ? 0 : (size_t)b * ostride);
    int row0 = blockIdx.x * 64, col0 = blockIdx.y * 128;
    int bT = b * TTi;

    int t = threadIdx.x, wid = t >> 5, lane = t & 31;
    int wm = (wid & 1) * 32, wn = (wid >> 1) * 32;
    uint32_t sbase = smem_u32(smraw);

    float acc[2][4][4];
#pragma unroll
    for (int mt = 0; mt < 2; mt++)
#pragma unroll
        for (int nt = 0; nt < 4; nt++)
#pragma unroll
            for (int q = 0; q < 4; q++) acc[mt][nt][q] = 0.f;

    uint32_t lmRow  = lane & 15;
    uint32_t lmColB = (lane >> 4) * 16;

    gp_load(sbase,            0,  row0, col0, bT, Ah, Al, Bh, Bl, ldb, bxmode);
    gp_load(sbase + GP_STAGE, 32, row0, col0, bT, Ah, Al, Bh, Bl, ldb, bxmode);

    int s0 = 0, s1 = 1, s2 = 2;
    for (int kt = 0; kt < 32; kt++) {
        if (kt < 31) { CP_WAIT1(); } else { CP_WAIT0(); }
        __syncthreads();
        if (kt + 2 < 32)
            gp_load(sbase + (uint32_t)s2 * GP_STAGE, (kt + 2) * 32, row0, col0, bT,
                    Ah, Al, Bh, Bl, ldb, bxmode);

        uint32_t so = sbase + (uint32_t)s0 * GP_STAGE;

        // ---- load ALL fragments for both k-halves first (16 ldsm burst) ----
        uint32_t ah[2][2][4], al[2][2][4];   // [ks][mt][4]
        uint32_t bh[2][2][4], bl[2][2][4];   // [ks][np][4]
#pragma unroll
        for (int ks = 0; ks < 2; ks++) {
#pragma unroll
            for (int mt = 0; mt < 2; mt++) {
                uint32_t ad = so + (wm + mt * 16 + lmRow) * 80 + ks * 32 + lmColB;
                ldm4(ah[ks][mt], ad);
                ldm4(al[ks][mt], ad + A_LO_OFF);
            }
#pragma unroll
            for (int np = 0; np < 2; np++) {
                uint32_t bd = so + B_OFF + (ks * 16 + lmRow) * 272 + (wn + np * 16) * 2 + lmColB;
                ldm4t(bh[ks][np], bd);
                ldm4t(bl[ks][np], bd + B_LO_OFF);
            }
        }
        // ---- uninterrupted mma burst (emission order identical to R11) ----
#pragma unroll
        for (int ks = 0; ks < 2; ks++)
#pragma unroll
            for (int np = 0; np < 2; np++)
#pragma unroll
                for (int mt = 0; mt < 2; mt++) {
                    mma_bf(acc[mt][2 * np],     ah[ks][mt], bh[ks][np][0], bh[ks][np][1]);
                    mma_bf(acc[mt][2 * np + 1], ah[ks][mt], bh[ks][np][2], bh[ks][np][3]);
                    mma_bf(acc[mt][2 * np],     ah[ks][mt], bl[ks][np][0], bl[ks][np][1]);
                    mma_bf(acc[mt][2 * np + 1], ah[ks][mt], bl[ks][np][2], bl[ks][np][3]);
                    mma_bf(acc[mt][2 * np],     al[ks][mt], bh[ks][np][0], bh[ks][np][1]);
                    mma_bf(acc[mt][2 * np + 1], al[ks][mt], bh[ks][np][2], bh[ks][np][3]);
                }

        int sx = s0; s0 = s1; s1 = s2; s2 = sx;
    }

    int gr = lane >> 2, gc = (lane & 3) * 2;
#pragma unroll
    for (int mt = 0; mt < 2; mt++)
#pragma unroll
        for (int nt = 0; nt < 4; nt++) {
            int r = row0 + wm + mt * 16 + gr;
            int c = col0 + wn + nt * 8 + gc;
#pragma unroll
            for (int half = 0; half < 2; half++) {
                int rr = r + half * 8;
                bf16 h0, l0, h1, l1;
                split_bf(acc[mt][nt][half * 2 + 0], h0, l0);
                split_bf(acc[mt][nt][half * 2 + 1], h1, l1);
                size_t off;
                if (oxmode) off = ((size_t)(bT + (c >> 4)) * NNi + rr) * 16 + (c & 15);
                else        off = (size_t)rr * ldo + c;
                *(__nv_bfloat162*)&Ohi[off] = __halves2bfloat162(h0, h1);
                *(__nv_bfloat162*)&Olo[off] = __halves2bfloat162(l0, l1);
            }
        }
}

// ------------------- dense HMMA pieces (M=128 tiles) -------------------
#define DH_A_STRIDE 80
#define DH_ALO_OFF  10240
#define DH_B_OFF    20480
#define DH_B_STRIDE 144
#define DH_BLO_OFF  4608
#define DH_STAGE    29696

__device__ __forceinline__ void dh_load_stage(
    uint32_t so, int k0, int row0, int z, int t, int col0, int Kdim, int afmt,
    const bf16* __restrict__ Hhi, const bf16* __restrict__ Hlo,
    const bf16* __restrict__ Whi, const bf16* __restrict__ Wlo, int Npad)
{
#pragma unroll
    for (int i = 0; i < 4; i++) {
        int c = threadIdx.x + i * 256;
        int arr = c >> 9, cc = c & 511;
        int row = cc >> 2, seg = cc & 3;
        int kk = k0 + seg * 8;
        int grow = row0 + row;
        const bf16* src; size_t off;
        if (afmt == 3) {
            src = arr ? Hlo : Hhi;
            off = (size_t)grow * 64 + kk;
        } else if (afmt == 1) {
            const bf16 *hi, *lo; int kloc;
            if (kk < 64)       { hi = g_Shi;  lo = g_Slo;  kloc = kk; }
            else if (kk < 128) { hi = g_B1hi; lo = g_B1lo; kloc = kk - 64; }
            else               { hi = g_B2hi; lo = g_B2lo; kloc = kk - 128; }
            src = arr ? lo : hi;
            off = (size_t)grow * 128 + z * 64 + kloc;
        } else {
            if (kk >= Kdim) { src = g_zero_bf; off = 0; }
            else {
                int bb = grow >> 10, n = grow & 1023;
                size_t xb = (((size_t)bb * TTi + t) * NNi + n) * 16;
                const bf16 *hi, *lo; size_t o2;
                if (kk < 16)       { hi = g_Xhi;   lo = g_Xlo;   o2 = xb + kk; }
                else if (kk < 80)  { hi = Hhi;     lo = Hlo;     o2 = (size_t)grow * 128 + z * 64 + (kk - 16); }
                else if (kk < 96)  { hi = g_AX1hi; lo = g_AX1lo; o2 = xb + (kk - 80); }
                else if (kk < 160) { hi = g_B1hi;  lo = g_B1lo;  o2 = (size_t)grow * 128 + z * 64 + (kk - 96); }
                else if (kk < 176) { hi = g_AX2hi; lo = g_AX2lo; o2 = xb + (kk - 160); }
                else               { hi = g_B2hi;  lo = g_B2lo;  o2 = (size_t)grow * 128 + z * 64 + (kk - 176); }
                src = arr ? lo : hi; off = o2;
            }
        }
        cpa16(so + arr * DH_ALO_OFF + row * DH_A_STRIDE + seg * 16, src + off);
    }
#pragma unroll
    for (int i = 0; i < 2; i++) {
        int c = threadIdx.x + i * 256;
        int arr = c >> 8, cc = c & 255;
        int k = cc >> 3, seg = cc & 7;
        const bf16* w = (arr ? Wlo : Whi) + (size_t)(k0 + k) * Npad + col0 + seg * 8;
        cpa16(so + DH_B_OFF + arr * DH_BLO_OFF + k * DH_B_STRIDE + seg * 16, w);
    }
    CP_COMMIT();
}

__device__ __forceinline__ void dh_epi(int mode, int z, int t, int row, int col, float v) {
    if (mode == 2) {
        float g = 1.f / (1.f + expf(-v));
        if (col < 64) {
            size_t ii = (size_t)row * 128 + z * 64 + col;
            float rh = g * g_S[ii];
            split_bf(rh, g_RHhi[ii], g_RHlo[ii]);
        } else {
            g_u[(size_t)row * 128 + z * 64 + (col - 64)] = g;
        }
    } else { // 3
        float cc = tanhf(v);
        size_t ii = (size_t)row * 128 + z * 64 + col;
        float u = g_u[ii], h = g_S[ii];
        float m = g_obs[((size_t)(row >> 10) * TTi + t) * NNi + (row & 1023)];
        float hn = u * h + (1.f - u) * cc;
        float s = h + m * (hn - h);
        g_S[ii] = s;
        split_bf(s, g_Shi[ii], g_Slo[ii]);
    }
}

// modes: 2 gate | 3 cand blend | 4 tanh->pair out | 5 sigmoid*hv_pre->pair out | 6 plain->d_out
__global__ void __launch_bounds__(256, 2) denseH_k(
    int afmt, int Kdim, int nkt, int mode, int t,
    const bf16* __restrict__ Hhi, const bf16* __restrict__ Hlo,
    const bf16* __restrict__ W0hi, const bf16* __restrict__ W0lo,
    const bf16* __restrict__ W1hi, const bf16* __restrict__ W1lo, int Npad,
    const float* __restrict__ bias0, const float* __restrict__ bias1,
    bf16* __restrict__ Ohi, bf16* __restrict__ Olo, float* __restrict__ out4)
{
    extern __shared__ char smraw[];
    int z = blockIdx.z;
    int row0 = blockIdx.x * 128;
    int col0 = blockIdx.y * 64;
    const bf16* Whi = z ? W1hi : W0hi;
    const bf16* Wlo = z ? W1lo : W0lo;
    const float* bias = z ? bias1 : bias0;

    int tid = threadIdx.x, wid = tid >> 5, lane = tid & 31;
    int wm = (wid & 3) * 32, wn = (wid >> 2) * 32;
    uint32_t sb = smem_u32(smraw);
    uint32_t lmRow = lane & 15, lmColB = (lane >> 4) * 16;

    float acc[2][4][4];
#pragma unroll
    for (int mt = 0; mt < 2; mt++)
#pragma unroll
        for (int nt = 0; nt < 4; nt++)
#pragma unroll
            for (int q = 0; q < 4; q++) acc[mt][nt][q] = 0.f;

    dh_load_stage(sb, 0, row0, z, t, col0, Kdim, afmt, Hhi, Hlo, Whi, Wlo, Npad);

    for (int kt = 0; kt < nkt; kt++) {
        if (kt + 1 < nkt)
            dh_load_stage(sb + ((kt + 1) & 1) * DH_STAGE, (kt + 1) * 32, row0, z, t, col0,
                          Kdim, afmt, Hhi, Hlo, Whi, Wlo, Npad);
        if (kt + 1 < nkt) { CP_WAIT1(); } else { CP_WAIT0(); }
        __syncthreads();

        uint32_t so = sb + (kt & 1) * DH_STAGE;
#pragma unroll
        for (int ks = 0; ks < 2; ks++) {
            uint32_t ah[2][4], al[2][4];
#pragma unroll
            for (int mt = 0; mt < 2; mt++) {
                uint32_t ad = so + (wm + mt * 16 + lmRow) * DH_A_STRIDE + ks * 32 + lmColB;
                ldm4(ah[mt], ad);
                ldm4(al[mt], ad + DH_ALO_OFF);
            }
#pragma unroll
            for (int np = 0; np < 2; np++) {
                uint32_t bd = so + DH_B_OFF + (ks * 16 + lmRow) * DH_B_STRIDE + (wn + np * 16) * 2 + lmColB;
                uint32_t bh[4], bl[4];
                ldm4t(bh, bd);
                ldm4t(bl, bd + DH_BLO_OFF);
#pragma unroll
                for (int mt = 0; mt < 2; mt++) {
                    mma_bf(acc[mt][2 * np],     ah[mt], bh[0], bh[1]);
                    mma_bf(acc[mt][2 * np + 1], ah[mt], bh[2], bh[3]);
                    mma_bf(acc[mt][2 * np],     ah[mt], bl[0], bl[1]);
                    mma_bf(acc[mt][2 * np + 1], ah[mt], bl[2], bl[3]);
                    mma_bf(acc[mt][2 * np],     al[mt], bh[0], bh[1]);
                    mma_bf(acc[mt][2 * np + 1], al[mt], bh[2], bh[3]);
                }
            }
        }
        __syncthreads();
    }

    int gr = lane >> 2, gc = (lane & 3) * 2;
#pragma unroll
    for (int mt = 0; mt < 2; mt++)
#pragma unroll
        for (int nt = 0; nt < 4; nt++) {
            int r = row0 + wm + mt * 16 + gr;
            int c = col0 + wn + nt * 8 + gc;
            if (mode <= 3) {
                dh_epi(mode, z, t, r,     c,     acc[mt][nt][0] + bias[c]);
                dh_epi(mode, z, t, r,     c + 1, acc[mt][nt][1] + bias[c + 1]);
                dh_epi(mode, z, t, r + 8, c,     acc[mt][nt][2] + bias[c]);
                dh_epi(mode, z, t, r + 8, c + 1, acc[mt][nt][3] + bias[c + 1]);
            } else if (mode == 4) {
#pragma unroll
                for (int half = 0; half < 2; half++) {
                    int rr = r + half * 8;
                    float v0 = tanhf(acc[mt][nt][half * 2 + 0] + bias[c]);
                    float v1 = tanhf(acc[mt][nt][half * 2 + 1] + bias[c + 1]);
                    bf16 h0, l0, h1, l1;
                    split_bf(v0, h0, l0); split_bf(v1, h1, l1);
                    size_t off = (size_t)rr * 64 + c;
                    *(__nv_bfloat162*)&Ohi[off] = __halves2bfloat162(h0, h1);
                    *(__nv_bfloat162*)&Olo[off] = __halves2bfloat162(l0, l1);
                }
            } else if (mode == 5) {
#pragma unroll
                for (int half = 0; half < 2; half++) {
                    int rr = r + half * 8;
                    float g0 = 1.f / (1.f + expf(-(acc[mt][nt][half * 2 + 0] + bias[c])));
                    float g1 = 1.f / (1.f + expf(-(acc[mt][nt][half * 2 + 1] + bias[c + 1])));
                    float v0 = g0 * g_pre[(size_t)(rr + ROWSi) * 128 + c];
                    float v1 = g1 * g_pre[(size_t)(rr + ROWSi) * 128 + c + 1];
                    bf16 h0, l0, h1, l1;
                    split_bf(v0, h0, l0); split_bf(v1, h1, l1);
                    size_t off = (size_t)rr * 64 + c;
                    *(__nv_bfloat162*)&Ohi[off] = __halves2bfloat162(h0, h1);
                    *(__nv_bfloat162*)&Olo[off] = __halves2bfloat162(l0, l1);
                }
            } else { // 6
#pragma unroll
                for (int half = 0; half < 2; half++) {
                    int rr = r + half * 8;
                    int tp = rr >> 13, bn = rr & 8191;
                    int bb = bn >> 10, n = bn & 1023;
                    size_t ob = (((size_t)bb * 39 + tp) * NNi + n) * 16;
                    if (c < 16)     out4[ob + c]     = acc[mt][nt][half * 2 + 0] + bias[c];
                    if (c + 1 < 16) out4[ob + c + 1] = acc[mt][nt][half * 2 + 1] + bias[c + 1];
                }
            }
        }
}

// ------------------- fused ODE step, 64-row tiles, 2+ CTAs/SM -------------------
#define OD_ALO   5120
#define OD_B     10240
#define OD_BLO   4608
#define OD_STAGE 19456
#define OD_H1HI  38912
#define OD_H1LO  48128
#define OD_SMEM  57344

__device__ __forceinline__ void ode_load64(
    uint32_t so, int k0, int row0, int z,
    const bf16* __restrict__ Whi, const bf16* __restrict__ Wlo)
{
#pragma unroll
    for (int i = 0; i < 2; i++) {
        int c = threadIdx.x + i * 256;
        int arr = c >> 8, cc = c & 255;
        int row = cc >> 2, seg = cc & 3;
        int kk = k0 + seg * 8;
        int grow = row0 + row;
        const bf16 *hi, *lo; int kloc;
        if (kk < 64)       { hi = g_Shi;  lo = g_Slo;  kloc = kk; }
        else if (kk < 128) { hi = g_B1hi; lo = g_B1lo; kloc = kk - 64; }
        else               { hi = g_B2hi; lo = g_B2lo; kloc = kk - 128; }
        const bf16* src = arr ? lo : hi;
        size_t off = (size_t)grow * 128 + z * 64 + kloc;
        cpa16(so + arr * OD_ALO + row * 80 + seg * 16, src + off);
    }
#pragma unroll
    for (int i = 0; i < 2; i++) {
        int c = threadIdx.x + i * 256;
        int arr = c >> 8, cc = c & 255;
        int k = cc >> 3, seg = cc & 7;
        const bf16* w = (arr ? Wlo : Whi) + (size_t)(k0 + k) * 64 + seg * 8;
        cpa16(so + OD_B + arr * OD_BLO + k * 144 + seg * 16, w);
    }
    CP_COMMIT();
}

__global__ void __launch_bounds__(256, 2) denseODE_k(
    int t_pre,
    const bf16* __restrict__ W0hi, const bf16* __restrict__ W0lo,
    const bf16* __restrict__ Wouthi, const bf16* __restrict__ Woutlo,
    const float* __restrict__ b0_0, const float* __restrict__ b0_1,
    const float* __restrict__ bo_0, const float* __restrict__ bo_1)
{
    extern __shared__ char smraw[];
    int z = blockIdx.z;
    int row0 = blockIdx.x * 64;
    const bf16* Whi = W0hi + (size_t)z * 12288;
    const bf16* Wlo = W0lo + (size_t)z * 12288;
    const bf16* WoH = Wouthi + (size_t)z * 4096;
    const bf16* WoL = Woutlo + (size_t)z * 4096;
    const float* b0 = z ? b0_1 : b0_0;
    const float* bo = z ? bo_1 : bo_0;

    int tid = threadIdx.x, wid = tid >> 5, lane = tid & 31;
    int wm = (wid & 3) * 16, wn = (wid >> 2) * 32;
    uint32_t sb = smem_u32(smraw);
    uint32_t lmRow = lane & 15, lmColB = (lane >> 4) * 16;
    int gr = lane >> 2, gc = (lane & 3) * 2;

    float acc[4][4];
#pragma unroll
    for (int nt = 0; nt < 4; nt++)
#pragma unroll
        for (int q = 0; q < 4; q++) acc[nt][q] = 0.f;

    ode_load64(sb, 0, row0, z, Whi, Wlo);
    for (int kt = 0; kt < 6; kt++) {
        if (kt < 5)
            ode_load64(sb + ((kt + 1) & 1) * OD_STAGE, (kt + 1) * 32, row0, z, Whi, Wlo);
        if (kt < 5) { CP_WAIT1(); } else { CP_WAIT0(); }
        __syncthreads();
        uint32_t so = sb + (kt & 1) * OD_STAGE;
#pragma unroll
        for (int ks = 0; ks < 2; ks++) {
            uint32_t ah[4], al[4];
            uint32_t ad = so + (wm + lmRow) * 80 + ks * 32 + lmColB;
            ldm4(ah, ad);
            ldm4(al, ad + OD_ALO);
#pragma unroll
            for (int np = 0; np < 2; np++) {
                uint32_t bd = so + OD_B + (ks * 16 + lmRow) * 144 + (wn + np * 16) * 2 + lmColB;
                uint32_t bh[4], bl[4];
                ldm4t(bh, bd);
                ldm4t(bl, bd + OD_BLO);
                mma_bf(acc[2 * np],     ah, bh[0], bh[1]);
                mma_bf(acc[2 * np + 1], ah, bh[2], bh[3]);
                mma_bf(acc[2 * np],     ah, bl[0], bl[1]);
                mma_bf(acc[2 * np + 1], ah, bl[2], bl[3]);
                mma_bf(acc[2 * np],     al, bh[0], bh[1]);
                mma_bf(acc[2 * np + 1], al, bh[2], bh[3]);
            }
        }
        __syncthreads();
    }

#pragma unroll
    for (int nt = 0; nt < 4; nt++) {
        int rl = wm + gr;
        int c = wn + nt * 8 + gc;
        float v0 = tanhf(acc[nt][0] + b0[c]);
        float v1 = tanhf(acc[nt][1] + b0[c + 1]);
        float v2 = tanhf(acc[nt][2] + b0[c]);
        float v3 = tanhf(acc[nt][3] + b0[c + 1]);
        bf16 h0, l0, h1, l1;
        split_bf(v0, h0, l0); split_bf(v1, h1, l1);
        *(__nv_bfloat162*)(smraw + OD_H1HI + rl * 144 + c * 2) = __halves2bfloat162(h0, h1);
        *(__nv_bfloat162*)(smraw + OD_H1LO + rl * 144 + c * 2) = __halves2bfloat162(l0, l1);
        split_bf(v2, h0, l0); split_bf(v3, h1, l1);
        *(__nv_bfloat162*)(smraw + OD_H1HI + (rl + 8) * 144 + c * 2) = __halves2bfloat162(h0, h1);
        *(__nv_bfloat162*)(smraw + OD_H1LO + (rl + 8) * 144 + c * 2) = __halves2bfloat162(l0, l1);
    }
    __syncthreads();

#pragma unroll
    for (int i = 0; i < 4; i++) {
        int c = tid + i * 256;
        int arr = c >> 9, cc = c & 511, k = cc >> 3, seg = cc & 7;
        *(uint4*)(smraw + arr * 9216 + k * 144 + seg * 16) =
            *(const uint4*)((arr ? WoL : WoH) + (size_t)k * 64 + seg * 8);
    }
    __syncthreads();

#pragma unroll
    for (int nt = 0; nt < 4; nt++)
#pragma unroll
        for (int q = 0; q < 4; q++) acc[nt][q] = 0.f;

#pragma unroll
    for (int ks = 0; ks < 4; ks++) {
        uint32_t ah[4], al[4];
        uint32_t ad = sb + OD_H1HI + (wm + lmRow) * 144 + ks * 32 + lmColB;
        ldm4(ah, ad);
        ldm4(al, ad + (OD_H1LO - OD_H1HI));
#pragma unroll
        for (int np = 0; np < 2; np++) {
            uint32_t bd = sb + (ks * 16 + lmRow) * 144 + (wn + np * 16) * 2 + lmColB;
            uint32_t bh[4], bl[4];
            ldm4t(bh, bd);
            ldm4t(bl, bd + 9216);
            mma_bf(acc[2 * np],     ah, bh[0], bh[1]);
            mma_bf(acc[2 * np + 1], ah, bh[2], bh[3]);
            mma_bf(acc[2 * np],     ah, bl[0], bl[1]);
            mma_bf(acc[2 * np + 1], ah, bl[2], bl[3]);
            mma_bf(acc[2 * np],     al, bh[0], bh[1]);
            mma_bf(acc[2 * np + 1], al, bh[2], bh[3]);
        }
    }

#pragma unroll
    for (int nt = 0; nt < 4; nt++) {
        int r = row0 + wm + gr;
        int c = wn + nt * 8 + gc;
#pragma unroll
        for (int q = 0; q < 4; q++) {
            int rr = r + (q >> 1) * 8;
            int cc = c + (q & 1);
            size_t ii = (size_t)rr * 128 + z * 64 + cc;
            float s = g_S[ii] + DT_SUB * tanhf(acc[nt][q] + bo[cc]);
            g_S[ii] = s;
            split_bf(s, g_Shi[ii], g_Slo[ii]);
            if (t_pre >= 0) {
                g_pre[(size_t)t_pre * ((size_t)ROWSi * 128) + ii] = s;
                if (t_pre >= 1 && z == 1) {
                    size_t pz = ((size_t)(t_pre - 1) * ROWSi + rr) * 64 + cc;
                    split_bf(s, g_preZhi[pz], g_preZlo[pz]);
                }
            }
        }
    }
}

// ------------------- host orchestration -------------------
extern "C" void kernel_launch(void* const* d_in, const int* in_sizes, int n_in,
                              void* d_out, int out_size) {
    const float* values  = (const float*)d_in[0];
    const float* masks   = (const float*)d_in[1];
    const float* A       = (const float*)d_in[2];
    const float* h0      = (const float*)d_in[3];
    const float* z0      = (const float*)d_in[4];
    const float* gV_Wg   = (const float*)d_in[5];
    const float* gV_bg   = (const float*)d_in[6];
    const float* gV_Wc   = (const float*)d_in[7];
    const float* gV_bc   = (const float*)d_in[8];
    const float* gG_Wg   = (const float*)d_in[9];
    const float* gG_bg   = (const float*)d_in[10];
    const float* gG_Wc   = (const float*)d_in[11];
    const float* gG_bc   = (const float*)d_in[12];
    const float* oV_W0   = (const float*)d_in[13];
    const float* oV_b0   = (const float*)d_in[14];
    const float* oV_Wout = (const float*)d_in[15];
    const float* oV_bout = (const float*)d_in[16];
    const float* oG_W0   = (const float*)d_in[17];
    const float* oG_b0   = (const float*)d_in[18];
    const float* oG_Wout = (const float*)d_in[19];
    const float* oG_bout = (const float*)d_in[20];
    const float* Wz1     = (const float*)d_in[21];
    const float* bz1     = (const float*)d_in[22];
    const float* Wz2     = (const float*)d_in[23];
    const float* bz2     = (const float*)d_in[24];
    const float* Wz3     = (const float*)d_in[25];
    const float* bz3     = (const float*)d_in[26];
    const float* Wo      = (const float*)d_in[27];
    const float* bo      = (const float*)d_in[28];

    bf16 *pAhi, *pAlo, *pA2hi, *pA2lo, *pShi, *pSlo, *pRHhi, *pRHlo;
    bf16 *pB1hi, *pB1lo, *pB2hi, *pB2lo, *pXhi, *pXlo;
    bf16 *pAX1hi, *pAX1lo, *pAX2hi, *pAX2lo;
    bf16 *pPZhi, *pPZlo, *pT1hi, *pT1lo, *pT2hi, *pT2lo;
    bf16 *pOW0hi, *pOW0lo, *pOWouthi, *pOWoutlo, *pGWghi, *pGWglo, *pGWchi, *pGWclo;
    bf16 *pHWhi, *pHWlo;
    cudaGetSymbolAddress((void**)&pAhi,  g_Ahi);
    cudaGetSymbolAddress((void**)&pAlo,  g_Alo);
    cudaGetSymbolAddress((void**)&pA2hi, g_A2hi);
    cudaGetSymbolAddress((void**)&pA2lo, g_A2lo);
    cudaGetSymbolAddress((void**)&pShi,  g_Shi);
    cudaGetSymbolAddress((void**)&pSlo,  g_Slo);
    cudaGetSymbolAddress((void**)&pRHhi, g_RHhi);
    cudaGetSymbolAddress((void**)&pRHlo, g_RHlo);
    cudaGetSymbolAddress((void**)&pB1hi, g_B1hi);
    cudaGetSymbolAddress((void**)&pB1lo, g_B1lo);
    cudaGetSymbolAddress((void**)&pB2hi, g_B2hi);
    cudaGetSymbolAddress((void**)&pB2lo, g_B2lo);
    cudaGetSymbolAddress((void**)&pXhi,  g_Xhi);
    cudaGetSymbolAddress((void**)&pXlo,  g_Xlo);
    cudaGetSymbolAddress((void**)&pAX1hi, g_AX1hi);
    cudaGetSymbolAddress((void**)&pAX1lo, g_AX1lo);
    cudaGetSymbolAddress((void**)&pAX2hi, g_AX2hi);
    cudaGetSymbolAddress((void**)&pAX2lo, g_AX2lo);
    cudaGetSymbolAddress((void**)&pPZhi, g_preZhi);
    cudaGetSymbolAddress((void**)&pPZlo, g_preZlo);
    cudaGetSymbolAddress((void**)&pT1hi, g_T1hi);
    cudaGetSymbolAddress((void**)&pT1lo, g_T1lo);
    cudaGetSymbolAddress((void**)&pT2hi, g_T2hi);
    cudaGetSymbolAddress((void**)&pT2lo, g_T2lo);
    cudaGetSymbolAddress((void**)&pOW0hi,   g_oW0hi);
    cudaGetSymbolAddress((void**)&pOW0lo,   g_oW0lo);
    cudaGetSymbolAddress((void**)&pOWouthi, g_oWouthi);
    cudaGetSymbolAddress((void**)&pOWoutlo, g_oWoutlo);
    cudaGetSymbolAddress((void**)&pGWghi,   g_gWghi);
    cudaGetSymbolAddress((void**)&pGWglo,   g_gWglo);
    cudaGetSymbolAddress((void**)&pGWchi,   g_gWchi);
    cudaGetSymbolAddress((void**)&pGWclo,   g_gWclo);
    cudaGetSymbolAddress((void**)&pHWhi,    g_hWhi);
    cudaGetSymbolAddress((void**)&pHWlo,    g_hWlo);

    const int GP3 = 3 * GP_STAGE;            // 82944
    const int DH_SMEM = 2 * DH_STAGE;        // 59392
    cudaFuncSetAttribute(gemmP_hmma, cudaFuncAttributeMaxDynamicSharedMemorySize, GP3);
    cudaFuncSetAttribute(denseH_k,   cudaFuncAttributeMaxDynamicSharedMemorySize, DH_SMEM);
    cudaFuncSetAttribute(denseODE_k, cudaFuncAttributeMaxDynamicSharedMemorySize, OD_SMEM);

    const size_t sAA = (size_t)NNi * NNi;
    const size_t sS  = (size_t)NNi * 128;

    initX_k<<<1280, 256>>>((const float4*)values, (const float4*)masks);            // 0
    initS_k<<<4096, 256>>>(h0, z0);                                                 // 1
    splitA_k<<<32768, 256>>>(A, pAhi, pAlo);                                        // 2
    gemmP_hmma<<<dim3(16, 8, 8), 256, GP3>>>(pAhi, pAlo, pAhi, pAlo,                // 3 (profiled)
        pAhi, pAlo, NNi, sAA, 0, pA2hi, pA2lo, pA2hi, pA2lo, NNi, sAA, 0);
    gemmP_hmma<<<dim3(16, 5, 16), 256, GP3>>>(pAhi, pAlo, pA2hi, pA2lo,
        pXhi, pXlo, 0, 0, 1, pAX1hi, pAX1lo, pAX2hi, pAX2lo, 0, 0, 1);
    gemmP_hmma<<<dim3(16, 1, 16), 256, GP3>>>(pAhi, pAlo, pA2hi, pA2lo,
        pShi, pSlo, 128, sS, 0, pB1hi, pB1lo, pB2hi, pB2lo, 128, sS, 0);
    splitW_k<<<48, 256>>>(oV_W0,   pOW0hi,           pOW0lo,           192, 64, 64);
    splitW_k<<<48, 256>>>(oG_W0,   pOW0hi + 12288,   pOW0lo + 12288,   192, 64, 64);
    splitW_k<<<16, 256>>>(oV_Wout, pOWouthi,         pOWoutlo,         64, 64, 64);
    splitW_k<<<16, 256>>>(oG_Wout, pOWouthi + 4096,  pOWoutlo + 4096,  64, 64, 64);
    splitW_k<<<128, 256>>>(gV_Wg,  pGWghi,           pGWglo,           240, 128, 128);
    splitW_k<<<128, 256>>>(gG_Wg,  pGWghi + 32768,   pGWglo + 32768,   240, 128, 128);
    splitW_k<<<64, 256>>>(gV_Wc,   pGWchi,           pGWclo,           240, 64, 64);
    splitW_k<<<64, 256>>>(gG_Wc,   pGWchi + 16384,   pGWclo + 16384,   240, 64, 64);
    splitW_k<<<16, 256>>>(Wz1, pHWhi,         pHWlo,         64, 64, 64);
    splitW_k<<<16, 256>>>(Wz2, pHWhi + 4096,  pHWlo + 4096,  64, 64, 64);
    splitW_k<<<16, 256>>>(Wz3, pHWhi + 8192,  pHWlo + 8192,  64, 64, 64);
    splitW_k<<<16, 256>>>(Wo,  pHWhi + 12288, pHWlo + 12288, 64, 16, 64);

    dim3 mmaG(16, 1, 16);
    for (int t = 0; t < TTi; t++) {
        for (int sub = 0; sub < 2; sub++) {
            if (t || sub)
                gemmP_hmma<<<mmaG, 256, GP3>>>(pAhi, pAlo, pA2hi, pA2lo,
                    pShi, pSlo, 128, sS, 0, pB1hi, pB1lo, pB2hi, pB2lo, 128, sS, 0);
            denseODE_k<<<dim3(128, 1, 2), 256, OD_SMEM>>>((sub == 1) ? t : -1,
                pOW0hi, pOW0lo, pOWouthi, pOWoutlo, oV_b0, oG_b0, oV_bout, oG_bout);
        }
        if (t < TTi - 1) {
            gemmP_hmma<<<mmaG, 256, GP3>>>(pAhi, pAlo, pA2hi, pA2lo,
                pShi, pSlo, 128, sS, 0, pB1hi, pB1lo, pB2hi, pB2lo, 128, sS, 0);
            denseH_k<<<dim3(64, 2, 2), 256, DH_SMEM>>>(2, 240, 8, 2, t,
                pShi, pSlo, pGWghi, pGWglo, pGWghi + 32768, pGWglo + 32768, 128,
                gV_bg, gG_bg, nullptr, nullptr, nullptr);
            gemmP_hmma<<<mmaG, 256, GP3>>>(pAhi, pAlo, pA2hi, pA2lo,
                pRHhi, pRHlo, 128, sS, 0, pB1hi, pB1lo, pB2hi, pB2lo, 128, sS, 0);
            denseH_k<<<dim3(64, 1, 2), 256, DH_SMEM>>>(2, 240, 8, 3, t,
                pRHhi, pRHlo, pGWchi, pGWclo, pGWchi + 16384, pGWclo + 16384, 64,
                gV_bc, gG_bc, nullptr, nullptr, nullptr);
        }
    }

    // Output head over t = 1..39
    denseH_k<<<dim3(2496, 1, 1), 256, DH_SMEM>>>(3, 64, 2, 4, 0,
        pPZhi, pPZlo, pHWhi, pHWlo, pHWhi, pHWlo, 64, bz1, bz1,
        pT1hi, pT1lo, nullptr);
    denseH_k<<<dim3(2496, 1, 1), 256, DH_SMEM>>>(3, 64, 2, 4, 0,
        pT1hi, pT1lo, pHWhi + 4096, pHWlo + 4096, pHWhi + 4096, pHWlo + 4096, 64, bz2, bz2,
        pT2hi, pT2lo, nullptr);
    denseH_k<<<dim3(2496, 1, 1), 256, DH_SMEM>>>(3, 64, 2, 5, 0,
        pT2hi, pT2lo, pHWhi + 8192, pHWlo + 8192, pHWhi + 8192, pHWlo + 8192, 64, bz3, bz3,
        pT1hi, pT1lo, nullptr);
    denseH_k<<<dim3(2496, 1, 1), 256, DH_SMEM>>>(3, 64, 2, 6, 0,
        pT1hi, pT1lo, pHWhi + 12288, pHWlo + 12288, pHWhi + 12288, pHWlo + 12288, 64, bo, bo,
        nullptr, nullptr, (float*)d_out);
}

// round 13
// speedup vs baseline: 1.0392x; 1.0392x over previous
#include <cuda_runtime.h>
#include <cuda_bf16.h>
#include <cstdint>

#define NNi   1024
#define BBi   8
#define TTi   40
#define DINi  16
#define ROWSi 8192
#define DT_SUB 0.025f

typedef __nv_bfloat16 bf16;

// ------------------- static scratch (no runtime allocation) -------------------
__device__ float g_obs[(size_t)BBi*TTi*NNi];
__device__ float g_S  [(size_t)ROWSi*128];
__device__ float g_u  [(size_t)ROWSi*128];
__device__ float g_pre[(size_t)TTi*ROWSi*128];
// bf16 split operand twins
__device__ bf16 g_Ahi  [(size_t)BBi*NNi*NNi];
__device__ bf16 g_Alo  [(size_t)BBi*NNi*NNi];
__device__ bf16 g_A2hi [(size_t)BBi*NNi*NNi];
__device__ bf16 g_A2lo [(size_t)BBi*NNi*NNi];
__device__ bf16 g_Shi  [(size_t)ROWSi*128];
__device__ bf16 g_Slo  [(size_t)ROWSi*128];
__device__ bf16 g_RHhi [(size_t)ROWSi*128];
__device__ bf16 g_RHlo [(size_t)ROWSi*128];
__device__ bf16 g_B1hi [(size_t)ROWSi*128];
__device__ bf16 g_B1lo [(size_t)ROWSi*128];
__device__ bf16 g_B2hi [(size_t)ROWSi*128];
__device__ bf16 g_B2lo [(size_t)ROWSi*128];
__device__ bf16 g_Xhi  [(size_t)BBi*TTi*NNi*DINi];
__device__ bf16 g_Xlo  [(size_t)BBi*TTi*NNi*DINi];
__device__ bf16 g_AX1hi[(size_t)BBi*TTi*NNi*DINi];
__device__ bf16 g_AX1lo[(size_t)BBi*TTi*NNi*DINi];
__device__ bf16 g_AX2hi[(size_t)BBi*TTi*NNi*DINi];
__device__ bf16 g_AX2lo[(size_t)BBi*TTi*NNi*DINi];
__device__ bf16 g_preZhi[(size_t)39*ROWSi*64];
__device__ bf16 g_preZlo[(size_t)39*ROWSi*64];
__device__ bf16 g_zero_bf[16];
// padded bf16 weight splits
__device__ bf16 g_oW0hi  [2*192*64];
__device__ bf16 g_oW0lo  [2*192*64];
__device__ bf16 g_oWouthi[2*64*64];
__device__ bf16 g_oWoutlo[2*64*64];
__device__ bf16 g_gWghi  [2*256*128];
__device__ bf16 g_gWglo  [2*256*128];
__device__ bf16 g_gWchi  [2*256*64];
__device__ bf16 g_gWclo  [2*256*64];
__device__ bf16 g_hWhi   [4*64*64];     // Wz1,Wz2,Wz3,Wo(pad)
__device__ bf16 g_hWlo   [4*64*64];

// ------------------- asm helpers -------------------
__device__ __forceinline__ uint32_t smem_u32(const void* p) {
    uint32_t a;
    asm("{ .reg .u64 t; cvta.to.shared.u64 t, %1; cvt.u32.u64 %0, t; }" : "=r"(a) : "l"(p));
    return a;
}
__device__ __forceinline__ void ldm4(uint32_t* r, uint32_t a) {
    asm volatile("ldmatrix.sync.aligned.m8n8.x4.shared.b16 {%0,%1,%2,%3}, [%4];"
        : "=r"(r[0]), "=r"(r[1]), "=r"(r[2]), "=r"(r[3]) : "r"(a));
}
__device__ __forceinline__ void ldm4t(uint32_t* r, uint32_t a) {
    asm volatile("ldmatrix.sync.aligned.m8n8.x4.trans.shared.b16 {%0,%1,%2,%3}, [%4];"
        : "=r"(r[0]), "=r"(r[1]), "=r"(r[2]), "=r"(r[3]) : "r"(a));
}
__device__ __forceinline__ void mma_bf(float* c, const uint32_t* a, uint32_t b0, uint32_t b1) {
    asm volatile("mma.sync.aligned.m16n8k16.row.col.f32.bf16.bf16.f32 "
        "{%0,%1,%2,%3}, {%4,%5,%6,%7}, {%8,%9}, {%0,%1,%2,%3};"
        : "+f"(c[0]), "+f"(c[1]), "+f"(c[2]), "+f"(c[3])
        : "r"(a[0]), "r"(a[1]), "r"(a[2]), "r"(a[3]), "r"(b0), "r"(b1));
}
__device__ __forceinline__ void cpa16(uint32_t sm, const void* gm) {
    asm volatile("cp.async.cg.shared.global [%0], [%1], 16;"
        :: "r"(sm), "l"(__cvta_generic_to_global(gm)));
}
#define CP_COMMIT() asm volatile("cp.async.commit_group;" ::: "memory")
#define CP_WAIT0()  asm volatile("cp.async.wait_group 0;" ::: "memory")
#define CP_WAIT1()  asm volatile("cp.async.wait_group 1;" ::: "memory")

__device__ __forceinline__ void split_bf(float v, bf16& h, bf16& l) {
    h = __float2bfloat16_rn(v);
    l = __float2bfloat16_rn(v - __bfloat162float(h));
}

// ------------------- init / split kernels -------------------
__global__ void initX_k(const float4* __restrict__ v, const float4* __restrict__ m) {
    int i = blockIdx.x * 256 + threadIdx.x;
    float s = 0.f;
#pragma unroll
    for (int q = 0; q < 4; q++) {
        float4 vv = v[i * 4 + q], mm = m[i * 4 + q];
        s += fabsf(mm.x) + fabsf(mm.y) + fabsf(mm.z) + fabsf(mm.w);
        float4 x = make_float4(vv.x * mm.x, vv.y * mm.y, vv.z * mm.z, vv.w * mm.w);
        size_t o = (size_t)i * 16 + q * 4;
        split_bf(x.x, g_Xhi[o + 0], g_Xlo[o + 0]);
        split_bf(x.y, g_Xhi[o + 1], g_Xlo[o + 1]);
        split_bf(x.z, g_Xhi[o + 2], g_Xlo[o + 2]);
        split_bf(x.w, g_Xhi[o + 3], g_Xlo[o + 3]);
    }
    g_obs[i] = (s > 1e-4f) ? 1.f : 0.f;
}
__global__ void initS_k(const float* __restrict__ h0, const float* __restrict__ z0) {
    int i = blockIdx.x * 256 + threadIdx.x;
    int c = i & 127;
    float v = (c < 64) ? h0[c] : z0[c - 64];
    g_S[i] = v;
    split_bf(v, g_Shi[i], g_Slo[i]);
}
__global__ void splitA_k(const float* __restrict__ src, bf16* __restrict__ hi, bf16* __restrict__ lo) {
    size_t i = (size_t)blockIdx.x * 256 + threadIdx.x;
    split_bf(src[i], hi[i], lo[i]);
}
__global__ void splitW_k(const float* __restrict__ src, bf16* __restrict__ hi, bf16* __restrict__ lo,
                         int K, int N, int Npad) {
    int i = blockIdx.x * 256 + threadIdx.x;
    int k = i / Npad, n = i - k * Npad;
    float v = (k < K && n < N) ? src[k * N + n] : 0.f;
    split_bf(v, hi[i], lo[i]);
}

// ------------------- diffusion GEMM (64x128 tile, K=1024, 3-stage) -------------------
#define GP_STAGE  27648
#define A_LO_OFF  5120
#define B_OFF     10240
#define B_LO_OFF  8704

__device__ __forceinline__ void gp_load(
    uint32_t so, int k0, int row0, int col0, int bT,
    const bf16* __restrict__ Ah, const bf16* __restrict__ Al,
    const bf16* __restrict__ Bh, const bf16* __restrict__ Bl,
    int ldb, int bxmode)
{
    int t = threadIdx.x;
#pragma unroll
    for (int i = 0; i < 2; i++) {
        int c = t + i * 256;
        int arr = c >> 8, cc = c & 255, row = cc >> 2, seg = cc & 3;
        const bf16* g = (arr ? Al : Ah) + (size_t)(row0 + row) * NNi + k0 + seg * 8;
        cpa16(so + arr * A_LO_OFF + row * 80 + seg * 16, g);
    }
#pragma unroll
    for (int i = 0; i < 4; i++) {
        int c = t + i * 256;
        int arr = c >> 9, cc = c & 511, k = cc >> 4, seg = cc & 15;
        size_t off;
        if (bxmode) {
            int col = col0 + seg * 8;
            off = ((size_t)(bT + (col >> 4)) * NNi + (k0 + k)) * 16 + (col & 15);
        } else {
            off = (size_t)(k0 + k) * ldb + col0 + seg * 8;
        }
        cpa16(so + B_OFF + arr * B_LO_OFF + k * 272 + seg * 16, (arr ? Bl : Bh) + off);
    }
    CP_COMMIT();
}

__global__ void __launch_bounds__(256, 2) gemmP_hmma(
    const bf16* __restrict__ Ahi1, const bf16* __restrict__ Alo1,
    const bf16* __restrict__ Ahi2, const bf16* __restrict__ Alo2,
    const bf16* __restrict__ Bhi, const bf16* __restrict__ Blo,
    int ldb, size_t bstride, int bxmode,
    bf16* __restrict__ O1hi, bf16* __restrict__ O1lo,
    bf16* __restrict__ O2hi, bf16* __restrict__ O2lo,
    int ldo, size_t ostride, int oxmode)
{
    extern __shared__ char smraw[];
    int bz = blockIdx.z;
    int b = bz & 7, hop = bz >> 3;
    const bf16* Ah = (hop ? Ahi2 : Ahi1) + (size_t)b * NNi * NNi;
    const bf16* Al = (hop ? Alo2 : Alo1) + (size_t)b * NNi * NNi;
    const bf16* Bh = bxmode ? Bhi : Bhi + (size_t)b * bstride;
    const bf16* Bl = bxmode ? Blo : Blo + (size_t)b * bstride;
    bf16* Ohi = (hop ? O2hi : O1hi) + (oxmode ? 0 : (size_t)b * ostride);
    bf16* Olo = (hop ? O2lo : O1lo) + (oxmode ? 0 : (size_t)b * ostride);
    int row0 = blockIdx.x * 64, col0 = blockIdx.y * 128;
    int bT = b * TTi;

    int t = threadIdx.x, wid = t >> 5, lane = t & 31;
    int wm = (wid & 1) * 32, wn = (wid >> 1) * 32;
    uint32_t sbase = smem_u32(smraw);

    float acc[2][4][4];
#pragma unroll
    for (int mt = 0; mt < 2; mt++)
#pragma unroll
        for (int nt = 0; nt < 4; nt++)
#pragma unroll
            for (int q = 0; q < 4; q++) acc[mt][nt][q] = 0.f;

    uint32_t lmRow  = lane & 15;
    uint32_t lmColB = (lane >> 4) * 16;

    gp_load(sbase,            0,  row0, col0, bT, Ah, Al, Bh, Bl, ldb, bxmode);
    gp_load(sbase + GP_STAGE, 32, row0, col0, bT, Ah, Al, Bh, Bl, ldb, bxmode);

    int s0 = 0, s1 = 1, s2 = 2;
    for (int kt = 0; kt < 32; kt++) {
        if (kt < 31) { CP_WAIT1(); } else { CP_WAIT0(); }
        __syncthreads();
        if (kt + 2 < 32)
            gp_load(sbase + (uint32_t)s2 * GP_STAGE, (kt + 2) * 32, row0, col0, bT,
                    Ah, Al, Bh, Bl, ldb, bxmode);

        uint32_t so = sbase + (uint32_t)s0 * GP_STAGE;
#pragma unroll
        for (int ks = 0; ks < 2; ks++) {
            uint32_t ah[2][4], al[2][4];
#pragma unroll
            for (int mt = 0; mt < 2; mt++) {
                uint32_t ad = so + (wm + mt * 16 + lmRow) * 80 + ks * 32 + lmColB;
                ldm4(ah[mt], ad);
                ldm4(al[mt], ad + A_LO_OFF);
            }
#pragma unroll
            for (int np = 0; np < 2; np++) {
                uint32_t bd = so + B_OFF + (ks * 16 + lmRow) * 272 + (wn + np * 16) * 2 + lmColB;
                uint32_t bh[4], bl[4];
                ldm4t(bh, bd);
                ldm4t(bl, bd + B_LO_OFF);
#pragma unroll
                for (int mt = 0; mt < 2; mt++) {
                    mma_bf(acc[mt][2 * np],     ah[mt], bh[0], bh[1]);
                    mma_bf(acc[mt][2 * np + 1], ah[mt], bh[2], bh[3]);
                    mma_bf(acc[mt][2 * np],     ah[mt], bl[0], bl[1]);
                    mma_bf(acc[mt][2 * np + 1], ah[mt], bl[2], bl[3]);
                    mma_bf(acc[mt][2 * np],     al[mt], bh[0], bh[1]);
                    mma_bf(acc[mt][2 * np + 1], al[mt], bh[2], bh[3]);
                }
            }
        }
        int sx = s0; s0 = s1; s1 = s2; s2 = sx;
    }

    int gr = lane >> 2, gc = (lane & 3) * 2;
#pragma unroll
    for (int mt = 0; mt < 2; mt++)
#pragma unroll
        for (int nt = 0; nt < 4; nt++) {
            int r = row0 + wm + mt * 16 + gr;
            int c = col0 + wn + nt * 8 + gc;
#pragma unroll
            for (int half = 0; half < 2; half++) {
                int rr = r + half * 8;
                bf16 h0, l0, h1, l1;
                split_bf(acc[mt][nt][half * 2 + 0], h0, l0);
                split_bf(acc[mt][nt][half * 2 + 1], h1, l1);
                size_t off;
                if (oxmode) off = ((size_t)(bT + (c >> 4)) * NNi + rr) * 16 + (c & 15);
                else        off = (size_t)rr * ldo + c;
                *(__nv_bfloat162*)&Ohi[off] = __halves2bfloat162(h0, h1);
                *(__nv_bfloat162*)&Olo[off] = __halves2bfloat162(l0, l1);
            }
        }
}

// ------------------- dense HMMA pieces (M=128 tiles, GRU gate/cand) -------------------
#define DH_A_STRIDE 80
#define DH_ALO_OFF  10240
#define DH_B_OFF    20480
#define DH_B_STRIDE 144
#define DH_BLO_OFF  4608
#define DH_STAGE    29696

__device__ __forceinline__ void dh_load_stage(
    uint32_t so, int k0, int row0, int z, int t, int col0, int Kdim,
    const bf16* __restrict__ Hhi, const bf16* __restrict__ Hlo,
    const bf16* __restrict__ Whi, const bf16* __restrict__ Wlo, int Npad)
{
#pragma unroll
    for (int i = 0; i < 4; i++) {
        int c = threadIdx.x + i * 256;
        int arr = c >> 9, cc = c & 511;
        int row = cc >> 2, seg = cc & 3;
        int kk = k0 + seg * 8;
        int grow = row0 + row;
        const bf16* src; size_t off;
        if (kk >= Kdim) { src = g_zero_bf; off = 0; }
        else {
            int bb = grow >> 10, n = grow & 1023;
            size_t xb = (((size_t)bb * TTi + t) * NNi + n) * 16;
            const bf16 *hi, *lo; size_t o2;
            if (kk < 16)       { hi = g_Xhi;   lo = g_Xlo;   o2 = xb + kk; }
            else if (kk < 80)  { hi = Hhi;     lo = Hlo;     o2 = (size_t)grow * 128 + z * 64 + (kk - 16); }
            else if (kk < 96)  { hi = g_AX1hi; lo = g_AX1lo; o2 = xb + (kk - 80); }
            else if (kk < 160) { hi = g_B1hi;  lo = g_B1lo;  o2 = (size_t)grow * 128 + z * 64 + (kk - 96); }
            else if (kk < 176) { hi = g_AX2hi; lo = g_AX2lo; o2 = xb + (kk - 160); }
            else               { hi = g_B2hi;  lo = g_B2lo;  o2 = (size_t)grow * 128 + z * 64 + (kk - 176); }
            src = arr ? lo : hi; off = o2;
        }
        cpa16(so + arr * DH_ALO_OFF + row * DH_A_STRIDE + seg * 16, src + off);
    }
#pragma unroll
    for (int i = 0; i < 2; i++) {
        int c = threadIdx.x + i * 256;
        int arr = c >> 8, cc = c & 255;
        int k = cc >> 3, seg = cc & 7;
        const bf16* w = (arr ? Wlo : Whi) + (size_t)(k0 + k) * Npad + col0 + seg * 8;
        cpa16(so + DH_B_OFF + arr * DH_BLO_OFF + k * DH_B_STRIDE + seg * 16, w);
    }
    CP_COMMIT();
}

__device__ __forceinline__ void dh_epi(int mode, int z, int t, int row, int col, float v) {
    if (mode == 2) {
        float g = 1.f / (1.f + expf(-v));
        if (col < 64) {
            size_t ii = (size_t)row * 128 + z * 64 + col;
            float rh = g * g_S[ii];
            split_bf(rh, g_RHhi[ii], g_RHlo[ii]);
        } else {
            g_u[(size_t)row * 128 + z * 64 + (col - 64)] = g;
        }
    } else { // 3
        float cc = tanhf(v);
        size_t ii = (size_t)row * 128 + z * 64 + col;
        float u = g_u[ii], h = g_S[ii];
        float m = g_obs[((size_t)(row >> 10) * TTi + t) * NNi + (row & 1023)];
        float hn = u * h + (1.f - u) * cc;
        float s = h + m * (hn - h);
        g_S[ii] = s;
        split_bf(s, g_Shi[ii], g_Slo[ii]);
    }
}

// modes: 2 gate | 3 cand blend
__global__ void __launch_bounds__(256, 2) denseH_k(
    int Kdim, int nkt, int mode, int t,
    const bf16* __restrict__ Hhi, const bf16* __restrict__ Hlo,
    const bf16* __restrict__ W0hi, const bf16* __restrict__ W0lo,
    const bf16* __restrict__ W1hi, const bf16* __restrict__ W1lo, int Npad,
    const float* __restrict__ bias0, const float* __restrict__ bias1)
{
    extern __shared__ char smraw[];
    int z = blockIdx.z;
    int row0 = blockIdx.x * 128;
    int col0 = blockIdx.y * 64;
    const bf16* Whi = z ? W1hi : W0hi;
    const bf16* Wlo = z ? W1lo : W0lo;
    const float* bias = z ? bias1 : bias0;

    int tid = threadIdx.x, wid = tid >> 5, lane = tid & 31;
    int wm = (wid & 3) * 32, wn = (wid >> 2) * 32;
    uint32_t sb = smem_u32(smraw);
    uint32_t lmRow = lane & 15, lmColB = (lane >> 4) * 16;

    float acc[2][4][4];
#pragma unroll
    for (int mt = 0; mt < 2; mt++)
#pragma unroll
        for (int nt = 0; nt < 4; nt++)
#pragma unroll
            for (int q = 0; q < 4; q++) acc[mt][nt][q] = 0.f;

    dh_load_stage(sb, 0, row0, z, t, col0, Kdim, Hhi, Hlo, Whi, Wlo, Npad);

    for (int kt = 0; kt < nkt; kt++) {
        if (kt + 1 < nkt)
            dh_load_stage(sb + ((kt + 1) & 1) * DH_STAGE, (kt + 1) * 32, row0, z, t, col0,
                          Kdim, Hhi, Hlo, Whi, Wlo, Npad);
        if (kt + 1 < nkt) { CP_WAIT1(); } else { CP_WAIT0(); }
        __syncthreads();

        uint32_t so = sb + (kt & 1) * DH_STAGE;
#pragma unroll
        for (int ks = 0; ks < 2; ks++) {
            uint32_t ah[2][4], al[2][4];
#pragma unroll
            for (int mt = 0; mt < 2; mt++) {
                uint32_t ad = so + (wm + mt * 16 + lmRow) * DH_A_STRIDE + ks * 32 + lmColB;
                ldm4(ah[mt], ad);
                ldm4(al[mt], ad + DH_ALO_OFF);
            }
#pragma unroll
            for (int np = 0; np < 2; np++) {
                uint32_t bd = so + DH_B_OFF + (ks * 16 + lmRow) * DH_B_STRIDE + (wn + np * 16) * 2 + lmColB;
                uint32_t bh[4], bl[4];
                ldm4t(bh, bd);
                ldm4t(bl, bd + DH_BLO_OFF);
#pragma unroll
                for (int mt = 0; mt < 2; mt++) {
                    mma_bf(acc[mt][2 * np],     ah[mt], bh[0], bh[1]);
                    mma_bf(acc[mt][2 * np + 1], ah[mt], bh[2], bh[3]);
                    mma_bf(acc[mt][2 * np],     ah[mt], bl[0], bl[1]);
                    mma_bf(acc[mt][2 * np + 1], ah[mt], bl[2], bl[3]);
                    mma_bf(acc[mt][2 * np],     al[mt], bh[0], bh[1]);
                    mma_bf(acc[mt][2 * np + 1], al[mt], bh[2], bh[3]);
                }
            }
        }
        __syncthreads();
    }

    int gr = lane >> 2, gc = (lane & 3) * 2;
#pragma unroll
    for (int mt = 0; mt < 2; mt++)
#pragma unroll
        for (int nt = 0; nt < 4; nt++) {
            int r = row0 + wm + mt * 16 + gr;
            int c = col0 + wn + nt * 8 + gc;
            dh_epi(mode, z, t, r,     c,     acc[mt][nt][0] + bias[c]);
            dh_epi(mode, z, t, r,     c + 1, acc[mt][nt][1] + bias[c + 1]);
            dh_epi(mode, z, t, r + 8, c,     acc[mt][nt][2] + bias[c]);
            dh_epi(mode, z, t, r + 8, c + 1, acc[mt][nt][3] + bias[c + 1]);
        }
}

// ------------------- fused ODE step, 64-row tiles -------------------
#define OD_ALO   5120
#define OD_B     10240
#define OD_BLO   4608
#define OD_STAGE 19456
#define OD_H1HI  38912
#define OD_H1LO  48128
#define OD_SMEM  57344

__device__ __forceinline__ void ode_load64(
    uint32_t so, int k0, int row0, int z,
    const bf16* __restrict__ Whi, const bf16* __restrict__ Wlo)
{
#pragma unroll
    for (int i = 0; i < 2; i++) {
        int c = threadIdx.x + i * 256;
        int arr = c >> 8, cc = c & 255;
        int row = cc >> 2, seg = cc & 3;
        int kk = k0 + seg * 8;
        int grow = row0 + row;
        const bf16 *hi, *lo; int kloc;
        if (kk < 64)       { hi = g_Shi;  lo = g_Slo;  kloc = kk; }
        else if (kk < 128) { hi = g_B1hi; lo = g_B1lo; kloc = kk - 64; }
        else               { hi = g_B2hi; lo = g_B2lo; kloc = kk - 128; }
        const bf16* src = arr ? lo : hi;
        size_t off = (size_t)grow * 128 + z * 64 + kloc;
        cpa16(so + arr * OD_ALO + row * 80 + seg * 16, src + off);
    }
#pragma unroll
    for (int i = 0; i < 2; i++) {
        int c = threadIdx.x + i * 256;
        int arr = c >> 8, cc = c & 255;
        int k = cc >> 3, seg = cc & 7;
        const bf16* w = (arr ? Wlo : Whi) + (size_t)(k0 + k) * 64 + seg * 8;
        cpa16(so + OD_B + arr * OD_BLO + k * 144 + seg * 16, w);
    }
    CP_COMMIT();
}

__global__ void __launch_bounds__(256, 2) denseODE_k(
    int t_pre,
    const bf16* __restrict__ W0hi, const bf16* __restrict__ W0lo,
    const bf16* __restrict__ Wouthi, const bf16* __restrict__ Woutlo,
    const float* __restrict__ b0_0, const float* __restrict__ b0_1,
    const float* __restrict__ bo_0, const float* __restrict__ bo_1)
{
    extern __shared__ char smraw[];
    int z = blockIdx.z;
    int row0 = blockIdx.x * 64;
    const bf16* Whi = W0hi + (size_t)z * 12288;
    const bf16* Wlo = W0lo + (size_t)z * 12288;
    const bf16* WoH = Wouthi + (size_t)z * 4096;
    const bf16* WoL = Woutlo + (size_t)z * 4096;
    const float* b0 = z ? b0_1 : b0_0;
    const float* bo = z ? bo_1 : bo_0;

    int tid = threadIdx.x, wid = tid >> 5, lane = tid & 31;
    int wm = (wid & 3) * 16, wn = (wid >> 2) * 32;
    uint32_t sb = smem_u32(smraw);
    uint32_t lmRow = lane & 15, lmColB = (lane >> 4) * 16;
    int gr = lane >> 2, gc = (lane & 3) * 2;

    float acc[4][4];
#pragma unroll
    for (int nt = 0; nt < 4; nt++)
#pragma unroll
        for (int q = 0; q < 4; q++) acc[nt][q] = 0.f;

    ode_load64(sb, 0, row0, z, Whi, Wlo);
    for (int kt = 0; kt < 6; kt++) {
        if (kt < 5)
            ode_load64(sb + ((kt + 1) & 1) * OD_STAGE, (kt + 1) * 32, row0, z, Whi, Wlo);
        if (kt < 5) { CP_WAIT1(); } else { CP_WAIT0(); }
        __syncthreads();
        uint32_t so = sb + (kt & 1) * OD_STAGE;
#pragma unroll
        for (int ks = 0; ks < 2; ks++) {
            uint32_t ah[4], al[4];
            uint32_t ad = so + (wm + lmRow) * 80 + ks * 32 + lmColB;
            ldm4(ah, ad);
            ldm4(al, ad + OD_ALO);
#pragma unroll
            for (int np = 0; np < 2; np++) {
                uint32_t bd = so + OD_B + (ks * 16 + lmRow) * 144 + (wn + np * 16) * 2 + lmColB;
                uint32_t bh[4], bl[4];
                ldm4t(bh, bd);
                ldm4t(bl, bd + OD_BLO);
                mma_bf(acc[2 * np],     ah, bh[0], bh[1]);
                mma_bf(acc[2 * np + 1], ah, bh[2], bh[3]);
                mma_bf(acc[2 * np],     ah, bl[0], bl[1]);
                mma_bf(acc[2 * np + 1], ah, bl[2], bl[3]);
                mma_bf(acc[2 * np],     al, bh[0], bh[1]);
                mma_bf(acc[2 * np + 1], al, bh[2], bh[3]);
            }
        }
        __syncthreads();
    }

#pragma unroll
    for (int nt = 0; nt < 4; nt++) {
        int rl = wm + gr;
        int c = wn + nt * 8 + gc;
        float v0 = tanhf(acc[nt][0] + b0[c]);
        float v1 = tanhf(acc[nt][1] + b0[c + 1]);
        float v2 = tanhf(acc[nt][2] + b0[c]);
        float v3 = tanhf(acc[nt][3] + b0[c + 1]);
        bf16 h0, l0, h1, l1;
        split_bf(v0, h0, l0); split_bf(v1, h1, l1);
        *(__nv_bfloat162*)(smraw + OD_H1HI + rl * 144 + c * 2) = __halves2bfloat162(h0, h1);
        *(__nv_bfloat162*)(smraw + OD_H1LO + rl * 144 + c * 2) = __halves2bfloat162(l0, l1);
        split_bf(v2, h0, l0); split_bf(v3, h1, l1);
        *(__nv_bfloat162*)(smraw + OD_H1HI + (rl + 8) * 144 + c * 2) = __halves2bfloat162(h0, h1);
        *(__nv_bfloat162*)(smraw + OD_H1LO + (rl + 8) * 144 + c * 2) = __halves2bfloat162(l0, l1);
    }
    __syncthreads();

    // copy Wout (64x64, hi+lo) into freed stage area: hi @0, lo @9216, stride 144
#pragma unroll
    for (int i = 0; i < 4; i++) {
        int c = tid + i * 256;
        int arr = c >> 9, cc = c & 511, k = cc >> 3, seg = cc & 7;
        *(uint4*)(smraw + arr * 9216 + k * 144 + seg * 16) =
            *(const uint4*)((arr ? WoL : WoH) + (size_t)k * 64 + seg * 8);
    }
    __syncthreads();

#pragma unroll
    for (int nt = 0; nt < 4; nt++)
#pragma unroll
        for (int q = 0; q < 4; q++) acc[nt][q] = 0.f;

#pragma unroll
    for (int ks = 0; ks < 4; ks++) {
        uint32_t ah[4], al[4];
        uint32_t ad = sb + OD_H1HI + (wm + lmRow) * 144 + ks * 32 + lmColB;
        ldm4(ah, ad);
        ldm4(al, ad + (OD_H1LO - OD_H1HI));
#pragma unroll
        for (int np = 0; np < 2; np++) {
            uint32_t bd = sb + (ks * 16 + lmRow) * 144 + (wn + np * 16) * 2 + lmColB;
            uint32_t bh[4], bl[4];
            ldm4t(bh, bd);
            ldm4t(bl, bd + 9216);
            mma_bf(acc[2 * np],     ah, bh[0], bh[1]);
            mma_bf(acc[2 * np + 1], ah, bh[2], bh[3]);
            mma_bf(acc[2 * np],     ah, bl[0], bl[1]);
            mma_bf(acc[2 * np + 1], ah, bl[2], bl[3]);
            mma_bf(acc[2 * np],     al, bh[0], bh[1]);
            mma_bf(acc[2 * np + 1], al, bh[2], bh[3]);
        }
    }

#pragma unroll
    for (int nt = 0; nt < 4; nt++) {
        int r = row0 + wm + gr;
        int c = wn + nt * 8 + gc;
#pragma unroll
        for (int q = 0; q < 4; q++) {
            int rr = r + (q >> 1) * 8;
            int cc = c + (q & 1);
            size_t ii = (size_t)rr * 128 + z * 64 + cc;
            float s = g_S[ii] + DT_SUB * tanhf(acc[nt][q] + bo[cc]);
            g_S[ii] = s;
            split_bf(s, g_Shi[ii], g_Slo[ii]);
            if (t_pre >= 1) {
                if (z == 0) {
                    g_pre[(size_t)t_pre * ((size_t)ROWSi * 128) + ii] = s;
                } else {
                    size_t pz = ((size_t)(t_pre - 1) * ROWSi + rr) * 64 + cc;
                    split_bf(s, g_preZhi[pz], g_preZlo[pz]);
                }
            }
        }
    }
}

// ------------------- fused output head: 4 chained row-local GEMMs -------------------
// smem: A pair [0,18432) | W pair [18432,36864) | T pair [36864,55296) | hvp fp32 [55296,71680)
#define HF_A    0
#define HF_ALO  9216
#define HF_W    18432
#define HF_WLO  27648
#define HF_T    36864
#define HF_TLO  46080
#define HF_HVP  55296
#define HF_SMEM 71680

__device__ __forceinline__ void hf_gemm(
    uint32_t sb, uint32_t aOff, uint32_t aLoDelta, float acc[4][4],
    int wm, int wn, uint32_t lmRow, uint32_t lmColB)
{
#pragma unroll
    for (int nt = 0; nt < 4; nt++)
#pragma unroll
        for (int q = 0; q < 4; q++) acc[nt][q] = 0.f;
#pragma unroll
    for (int ks = 0; ks < 4; ks++) {
        uint32_t ah[4], al[4];
        uint32_t ad = sb + aOff + (wm + lmRow) * 144 + ks * 32 + lmColB;
        ldm4(ah, ad);
        ldm4(al, ad + aLoDelta);
#pragma unroll
        for (int np = 0; np < 2; np++) {
            uint32_t bd = sb + HF_W + (ks * 16 + lmRow) * 144 + (wn + np * 16) * 2 + lmColB;
            uint32_t bh[4], bl[4];
            ldm4t(bh, bd);
            ldm4t(bl, bd + 9216);
            mma_bf(acc[2 * np],     ah, bh[0], bh[1]);
            mma_bf(acc[2 * np + 1], ah, bh[2], bh[3]);
            mma_bf(acc[2 * np],     ah, bl[0], bl[1]);
            mma_bf(acc[2 * np + 1], ah, bl[2], bl[3]);
            mma_bf(acc[2 * np],     al, bh[0], bh[1]);
            mma_bf(acc[2 * np + 1], al, bh[2], bh[3]);
        }
    }
}

__device__ __forceinline__ void hf_wcopy(char* smraw, int tid, const bf16* Whi, const bf16* Wlo) {
#pragma unroll
    for (int i = 0; i < 4; i++) {
        int c = tid + i * 256;
        int arr = c >> 9, cc = c & 511, k = cc >> 3, seg = cc & 7;
        *(uint4*)(smraw + HF_W + arr * 9216 + k * 144 + seg * 16) =
            *(const uint4*)((arr ? Wlo : Whi) + (size_t)k * 64 + seg * 8);
    }
}

__global__ void __launch_bounds__(256, 2) headF_k(
    const float* __restrict__ bz1, const float* __restrict__ bz2,
    const float* __restrict__ bz3, const float* __restrict__ boo,
    float* __restrict__ out4)
{
    extern __shared__ char smraw[];
    int row0 = blockIdx.x * 64;   // rows in [0, 319488)
    int tid = threadIdx.x, wid = tid >> 5, lane = tid & 31;
    int wm = (wid & 3) * 16, wn = (wid >> 2) * 32;
    uint32_t sb = smem_u32(smraw);
    uint32_t lmRow = lane & 15, lmColB = (lane >> 4) * 16;
    int gr = lane >> 2, gc = (lane & 3) * 2;

    // stage zv_pre pair (A), Wz1 pair, hv_pre fp32
#pragma unroll
    for (int i = 0; i < 4; i++) {   // A: 1024 chunks
        int c = tid + i * 256;
        int arr = c >> 9, cc = c & 511, row = cc >> 3, seg = cc & 7;
        const bf16* src = (arr ? g_preZlo : g_preZhi) + (size_t)(row0 + row) * 64 + seg * 8;
        cpa16(sb + HF_A + arr * 9216 + row * 144 + seg * 16, src);
    }
#pragma unroll
    for (int i = 0; i < 4; i++) {   // Wz1: 1024 chunks
        int c = tid + i * 256;
        int arr = c >> 9, cc = c & 511, k = cc >> 3, seg = cc & 7;
        const bf16* w = (arr ? g_hWlo : g_hWhi) + (size_t)k * 64 + seg * 8;
        cpa16(sb + HF_W + arr * 9216 + k * 144 + seg * 16, w);
    }
#pragma unroll
    for (int i = 0; i < 4; i++) {   // hv_pre: 1024 chunks of 16B
        int c = tid + i * 256;
        int row = c >> 4, seg = c & 15;
        const float* src = &g_pre[(size_t)(row0 + row + ROWSi) * 128 + seg * 4];
        cpa16(sb + HF_HVP + row * 256 + seg * 16, src);
    }
    CP_COMMIT();
    CP_WAIT0();
    __syncthreads();

    float acc[4][4];
    // ---- T1 = tanh(zv @ Wz1 + bz1) -> HF_T ----
    hf_gemm(sb, HF_A, 9216, acc, wm, wn, lmRow, lmColB);
#pragma unroll
    for (int nt = 0; nt < 4; nt++) {
        int rl = wm + gr;
        int c = wn + nt * 8 + gc;
        float v0 = tanhf(acc[nt][0] + bz1[c]);
        float v1 = tanhf(acc[nt][1] + bz1[c + 1]);
        float v2 = tanhf(acc[nt][2] + bz1[c]);
        float v3 = tanhf(acc[nt][3] + bz1[c + 1]);
        bf16 h0, l0, h1, l1;
        split_bf(v0, h0, l0); split_bf(v1, h1, l1);
        *(__nv_bfloat162*)(smraw + HF_T   + rl * 144 + c * 2) = __halves2bfloat162(h0, h1);
        *(__nv_bfloat162*)(smraw + HF_TLO + rl * 144 + c * 2) = __halves2bfloat162(l0, l1);
        split_bf(v2, h0, l0); split_bf(v3, h1, l1);
        *(__nv_bfloat162*)(smraw + HF_T   + (rl + 8) * 144 + c * 2) = __halves2bfloat162(h0, h1);
        *(__nv_bfloat162*)(smraw + HF_TLO + (rl + 8) * 144 + c * 2) = __halves2bfloat162(l0, l1);
    }
    __syncthreads();

    // ---- T2 = tanh(T1 @ Wz2 + bz2) -> HF_A (reuse) ----
    hf_wcopy(smraw, tid, g_hWhi + 4096, g_hWlo + 4096);
    __syncthreads();
    hf_gemm(sb, HF_T, 9216, acc, wm, wn, lmRow, lmColB);
#pragma unroll
    for (int nt = 0; nt < 4; nt++) {
        int rl = wm + gr;
        int c = wn + nt * 8 + gc;
        float v0 = tanhf(acc[nt][0] + bz2[c]);
        float v1 = tanhf(acc[nt][1] + bz2[c + 1]);
        float v2 = tanhf(acc[nt][2] + bz2[c]);
        float v3 = tanhf(acc[nt][3] + bz2[c + 1]);
        bf16 h0, l0, h1, l1;
        split_bf(v0, h0, l0); split_bf(v1, h1, l1);
        *(__nv_bfloat162*)(smraw + HF_A   + rl * 144 + c * 2) = __halves2bfloat162(h0, h1);
        *(__nv_bfloat162*)(smraw + HF_ALO + rl * 144 + c * 2) = __halves2bfloat162(l0, l1);
        split_bf(v2, h0, l0); split_bf(v3, h1, l1);
        *(__nv_bfloat162*)(smraw + HF_A   + (rl + 8) * 144 + c * 2) = __halves2bfloat162(h0, h1);
        *(__nv_bfloat162*)(smraw + HF_ALO + (rl + 8) * 144 + c * 2) = __halves2bfloat162(l0, l1);
    }
    __syncthreads();

    // ---- Tg = sigmoid(T2 @ Wz3 + bz3) * hv_pre -> HF_T ----
    hf_wcopy(smraw, tid, g_hWhi + 8192, g_hWlo + 8192);
    __syncthreads();
    hf_gemm(sb, HF_A, 9216, acc, wm, wn, lmRow, lmColB);
#pragma unroll
    for (int nt = 0; nt < 4; nt++) {
        int rl = wm + gr;
        int c = wn + nt * 8 + gc;
#pragma unroll
        for (int q = 0; q < 4; q++) {
            int rrl = rl + (q >> 1) * 8;
            int cc = c + (q & 1);
            float g = 1.f / (1.f + expf(-(acc[nt][q] + bz3[cc])));
            float v = g * *(const float*)(smraw + HF_HVP + rrl * 256 + cc * 4);
            bf16 h0, l0;
            split_bf(v, h0, l0);
            *(bf16*)(smraw + HF_T   + rrl * 144 + cc * 2) = h0;
            *(bf16*)(smraw + HF_TLO + rrl * 144 + cc * 2) = l0;
        }
    }
    __syncthreads();

    // ---- out = Tg @ Wo + bo -> d_out remapped ----
    hf_wcopy(smraw, tid, g_hWhi + 12288, g_hWlo + 12288);
    __syncthreads();
    hf_gemm(sb, HF_T, 9216, acc, wm, wn, lmRow, lmColB);
#pragma unroll
    for (int nt = 0; nt < 4; nt++) {
        int c = wn + nt * 8 + gc;
#pragma unroll
        for (int q = 0; q < 4; q++) {
            int cc = c + (q & 1);
            if (cc >= 16) continue;
            int rr = row0 + wm + gr + (q >> 1) * 8;
            int tp = rr >> 13, bn = rr & 8191;
            int bb = bn >> 10, n = bn & 1023;
            out4[(((size_t)bb * 39 + tp) * NNi + n) * 16 + cc] = acc[nt][q] + boo[cc];
        }
    }
}

// ------------------- host orchestration -------------------
extern "C" void kernel_launch(void* const* d_in, const int* in_sizes, int n_in,
                              void* d_out, int out_size) {
    const float* values  = (const float*)d_in[0];
    const float* masks   = (const float*)d_in[1];
    const float* A       = (const float*)d_in[2];
    const float* h0      = (const float*)d_in[3];
    const float* z0      = (const float*)d_in[4];
    const float* gV_Wg   = (const float*)d_in[5];
    const float* gV_bg   = (const float*)d_in[6];
    const float* gV_Wc   = (const float*)d_in[7];
    const float* gV_bc   = (const float*)d_in[8];
    const float* gG_Wg   = (const float*)d_in[9];
    const float* gG_bg   = (const float*)d_in[10];
    const float* gG_Wc   = (const float*)d_in[11];
    const float* gG_bc   = (const float*)d_in[12];
    const float* oV_W0   = (const float*)d_in[13];
    const float* oV_b0   = (const float*)d_in[14];
    const float* oV_Wout = (const float*)d_in[15];
    const float* oV_bout = (const float*)d_in[16];
    const float* oG_W0   = (const float*)d_in[17];
    const float* oG_b0   = (const float*)d_in[18];
    const float* oG_Wout = (const float*)d_in[19];
    const float* oG_bout = (const float*)d_in[20];
    const float* Wz1     = (const float*)d_in[21];
    const float* bz1     = (const float*)d_in[22];
    const float* Wz2     = (const float*)d_in[23];
    const float* bz2     = (const float*)d_in[24];
    const float* Wz3     = (const float*)d_in[25];
    const float* bz3     = (const float*)d_in[26];
    const float* Wo      = (const float*)d_in[27];
    const float* bo      = (const float*)d_in[28];

    bf16 *pAhi, *pAlo, *pA2hi, *pA2lo, *pShi, *pSlo, *pRHhi, *pRHlo;
    bf16 *pB1hi, *pB1lo, *pB2hi, *pB2lo, *pXhi, *pXlo;
    bf16 *pAX1hi, *pAX1lo, *pAX2hi, *pAX2lo;
    bf16 *pOW0hi, *pOW0lo, *pOWouthi, *pOWoutlo, *pGWghi, *pGWglo, *pGWchi, *pGWclo;
    bf16 *pHWhi, *pHWlo;
    cudaGetSymbolAddress((void**)&pAhi,  g_Ahi);
    cudaGetSymbolAddress((void**)&pAlo,  g_Alo);
    cudaGetSymbolAddress((void**)&pA2hi, g_A2hi);
    cudaGetSymbolAddress((void**)&pA2lo, g_A2lo);
    cudaGetSymbolAddress((void**)&pShi,  g_Shi);
    cudaGetSymbolAddress((void**)&pSlo,  g_Slo);
    cudaGetSymbolAddress((void**)&pRHhi, g_RHhi);
    cudaGetSymbolAddress((void**)&pRHlo, g_RHlo);
    cudaGetSymbolAddress((void**)&pB1hi, g_B1hi);
    cudaGetSymbolAddress((void**)&pB1lo, g_B1lo);
    cudaGetSymbolAddress((void**)&pB2hi, g_B2hi);
    cudaGetSymbolAddress((void**)&pB2lo, g_B2lo);
    cudaGetSymbolAddress((void**)&pXhi,  g_Xhi);
    cudaGetSymbolAddress((void**)&pXlo,  g_Xlo);
    cudaGetSymbolAddress((void**)&pAX1hi, g_AX1hi);
    cudaGetSymbolAddress((void**)&pAX1lo, g_AX1lo);
    cudaGetSymbolAddress((void**)&pAX2hi, g_AX2hi);
    cudaGetSymbolAddress((void**)&pAX2lo, g_AX2lo);
    cudaGetSymbolAddress((void**)&pOW0hi,   g_oW0hi);
    cudaGetSymbolAddress((void**)&pOW0lo,   g_oW0lo);
    cudaGetSymbolAddress((void**)&pOWouthi, g_oWouthi);
    cudaGetSymbolAddress((void**)&pOWoutlo, g_oWoutlo);
    cudaGetSymbolAddress((void**)&pGWghi,   g_gWghi);
    cudaGetSymbolAddress((void**)&pGWglo,   g_gWglo);
    cudaGetSymbolAddress((void**)&pGWchi,   g_gWchi);
    cudaGetSymbolAddress((void**)&pGWclo,   g_gWclo);
    cudaGetSymbolAddress((void**)&pHWhi,    g_hWhi);
    cudaGetSymbolAddress((void**)&pHWlo,    g_hWlo);

    const int GP3 = 3 * GP_STAGE;            // 82944
    const int DH_SMEM = 2 * DH_STAGE;        // 59392
    cudaFuncSetAttribute(gemmP_hmma, cudaFuncAttributeMaxDynamicSharedMemorySize, GP3);
    cudaFuncSetAttribute(denseH_k,   cudaFuncAttributeMaxDynamicSharedMemorySize, DH_SMEM);
    cudaFuncSetAttribute(denseODE_k, cudaFuncAttributeMaxDynamicSharedMemorySize, OD_SMEM);
    cudaFuncSetAttribute(headF_k,    cudaFuncAttributeMaxDynamicSharedMemorySize, HF_SMEM);

    const size_t sAA = (size_t)NNi * NNi;
    const size_t sS  = (size_t)NNi * 128;

    initX_k<<<1280, 256>>>((const float4*)values, (const float4*)masks);            // 0
    initS_k<<<4096, 256>>>(h0, z0);                                                 // 1
    splitA_k<<<32768, 256>>>(A, pAhi, pAlo);                                        // 2
    gemmP_hmma<<<dim3(16, 8, 8), 256, GP3>>>(pAhi, pAlo, pAhi, pAlo,                // 3 (profiled)
        pAhi, pAlo, NNi, sAA, 0, pA2hi, pA2lo, pA2hi, pA2lo, NNi, sAA, 0);
    gemmP_hmma<<<dim3(16, 5, 16), 256, GP3>>>(pAhi, pAlo, pA2hi, pA2lo,
        pXhi, pXlo, 0, 0, 1, pAX1hi, pAX1lo, pAX2hi, pAX2lo, 0, 0, 1);
    gemmP_hmma<<<dim3(16, 1, 16), 256, GP3>>>(pAhi, pAlo, pA2hi, pA2lo,
        pShi, pSlo, 128, sS, 0, pB1hi, pB1lo, pB2hi, pB2lo, 128, sS, 0);
    splitW_k<<<48, 256>>>(oV_W0,   pOW0hi,           pOW0lo,           192, 64, 64);
    splitW_k<<<48, 256>>>(oG_W0,   pOW0hi + 12288,   pOW0lo + 12288,   192, 64, 64);
    splitW_k<<<16, 256>>>(oV_Wout, pOWouthi,         pOWoutlo,         64, 64, 64);
    splitW_k<<<16, 256>>>(oG_Wout, pOWouthi + 4096,  pOWoutlo + 4096,  64, 64, 64);
    splitW_k<<<128, 256>>>(gV_Wg,  pGWghi,           pGWglo,           240, 128, 128);
    splitW_k<<<128, 256>>>(gG_Wg,  pGWghi + 32768,   pGWglo + 32768,   240, 128, 128);
    splitW_k<<<64, 256>>>(gV_Wc,   pGWchi,           pGWclo,           240, 64, 64);
    splitW_k<<<64, 256>>>(gG_Wc,   pGWchi + 16384,   pGWclo + 16384,   240, 64, 64);
    splitW_k<<<16, 256>>>(Wz1, pHWhi,         pHWlo,         64, 64, 64);
    splitW_k<<<16, 256>>>(Wz2, pHWhi + 4096,  pHWlo + 4096,  64, 64, 64);
    splitW_k<<<16, 256>>>(Wz3, pHWhi + 8192,  pHWlo + 8192,  64, 64, 64);
    splitW_k<<<16, 256>>>(Wo,  pHWhi + 12288, pHWlo + 12288, 64, 16, 64);

    dim3 mmaG(16, 1, 16);
    for (int t = 0; t < TTi; t++) {
        for (int sub = 0; sub < 2; sub++) {
            if (t || sub)
                gemmP_hmma<<<mmaG, 256, GP3>>>(pAhi, pAlo, pA2hi, pA2lo,
                    pShi, pSlo, 128, sS, 0, pB1hi, pB1lo, pB2hi, pB2lo, 128, sS, 0);
            denseODE_k<<<dim3(128, 1, 2), 256, OD_SMEM>>>((sub == 1) ? t : -1,
                pOW0hi, pOW0lo, pOWouthi, pOWoutlo, oV_b0, oG_b0, oV_bout, oG_bout);
        }
        if (t < TTi - 1) {
            gemmP_hmma<<<mmaG, 256, GP3>>>(pAhi, pAlo, pA2hi, pA2lo,
                pShi, pSlo, 128, sS, 0, pB1hi, pB1lo, pB2hi, pB2lo, 128, sS, 0);
            denseH_k<<<dim3(64, 2, 2), 256, DH_SMEM>>>(240, 8, 2, t,
                pShi, pSlo, pGWghi, pGWglo, pGWghi + 32768, pGWglo + 32768, 128,
                gV_bg, gG_bg);
            gemmP_hmma<<<mmaG, 256, GP3>>>(pAhi, pAlo, pA2hi, pA2lo,
                pRHhi, pRHlo, 128, sS, 0, pB1hi, pB1lo, pB2hi, pB2lo, 128, sS, 0);
            denseH_k<<<dim3(64, 1, 2), 256, DH_SMEM>>>(240, 8, 3, t,
                pRHhi, pRHlo, pGWchi, pGWclo, pGWchi + 16384, pGWclo + 16384, 64,
                gV_bc, gG_bc);
        }
    }

    // fused output head over t = 1..39 (rows 319488 = 4992 * 64)
    headF_k<<<4992, 256, HF_SMEM>>>(bz1, bz2, bz3, bo, (float*)d_out);
}

// round 15
// speedup vs baseline: 1.1051x; 1.0634x over previous
#include <cuda_runtime.h>
#include <cuda_bf16.h>
#include <cstdint>

#define NNi   1024
#define BBi   8
#define TTi   40
#define DINi  16
#define ROWSi 8192
#define DT_SUB 0.025f

typedef __nv_bfloat16 bf16;

// ------------------- static scratch (no runtime allocation) -------------------
__device__ float g_obs[(size_t)BBi*TTi*NNi];
__device__ float g_S  [(size_t)ROWSi*128];
__device__ float g_u  [(size_t)ROWSi*128];
__device__ float g_pre[(size_t)TTi*ROWSi*128];
// bf16 split operand twins
__device__ bf16 g_Ahi  [(size_t)BBi*NNi*NNi];
__device__ bf16 g_Alo  [(size_t)BBi*NNi*NNi];
__device__ bf16 g_A2hi [(size_t)BBi*NNi*NNi];
__device__ bf16 g_A2lo [(size_t)BBi*NNi*NNi];
__device__ bf16 g_Shi  [(size_t)ROWSi*128];
__device__ bf16 g_Slo  [(size_t)ROWSi*128];
__device__ bf16 g_RHhi [(size_t)ROWSi*128];
__device__ bf16 g_RHlo [(size_t)ROWSi*128];
__device__ bf16 g_B1hi [(size_t)ROWSi*128];
__device__ bf16 g_B1lo [(size_t)ROWSi*128];
__device__ bf16 g_B2hi [(size_t)ROWSi*128];
__device__ bf16 g_B2lo [(size_t)ROWSi*128];
__device__ bf16 g_Xhi  [(size_t)BBi*TTi*NNi*DINi];
__device__ bf16 g_Xlo  [(size_t)BBi*TTi*NNi*DINi];
__device__ bf16 g_AX1hi[(size_t)BBi*TTi*NNi*DINi];
__device__ bf16 g_AX1lo[(size_t)BBi*TTi*NNi*DINi];
__device__ bf16 g_AX2hi[(size_t)BBi*TTi*NNi*DINi];
__device__ bf16 g_AX2lo[(size_t)BBi*TTi*NNi*DINi];
__device__ bf16 g_preZhi[(size_t)39*ROWSi*64];
__device__ bf16 g_preZlo[(size_t)39*ROWSi*64];
__device__ bf16 g_zero_bf[16];
// padded bf16 weight splits
__device__ bf16 g_oW0hi  [2*192*64];
__device__ bf16 g_oW0lo  [2*192*64];
__device__ bf16 g_oWouthi[2*64*64];
__device__ bf16 g_oWoutlo[2*64*64];
__device__ bf16 g_gWghi  [2*256*128];
__device__ bf16 g_gWglo  [2*256*128];
__device__ bf16 g_gWchi  [2*256*64];
__device__ bf16 g_gWclo  [2*256*64];
__device__ bf16 g_hWhi   [4*64*64];     // Wz1,Wz2,Wz3,Wo(pad)
__device__ bf16 g_hWlo   [4*64*64];

// ------------------- asm helpers -------------------
__device__ __forceinline__ uint32_t smem_u32(const void* p) {
    uint32_t a;
    asm("{ .reg .u64 t; cvta.to.shared.u64 t, %1; cvt.u32.u64 %0, t; }" : "=r"(a) : "l"(p));
    return a;
}
__device__ __forceinline__ void ldm4(uint32_t* r, uint32_t a) {
    asm volatile("ldmatrix.sync.aligned.m8n8.x4.shared.b16 {%0,%1,%2,%3}, [%4];"
        : "=r"(r[0]), "=r"(r[1]), "=r"(r[2]), "=r"(r[3]) : "r"(a));
}
__device__ __forceinline__ void ldm4t(uint32_t* r, uint32_t a) {
    asm volatile("ldmatrix.sync.aligned.m8n8.x4.trans.shared.b16 {%0,%1,%2,%3}, [%4];"
        : "=r"(r[0]), "=r"(r[1]), "=r"(r[2]), "=r"(r[3]) : "r"(a));
}
__device__ __forceinline__ void mma_bf(float* c, const uint32_t* a, uint32_t b0, uint32_t b1) {
    asm volatile("mma.sync.aligned.m16n8k16.row.col.f32.bf16.bf16.f32 "
        "{%0,%1,%2,%3}, {%4,%5,%6,%7}, {%8,%9}, {%0,%1,%2,%3};"
        : "+f"(c[0]), "+f"(c[1]), "+f"(c[2]), "+f"(c[3])
        : "r"(a[0]), "r"(a[1]), "r"(a[2]), "r"(a[3]), "r"(b0), "r"(b1));
}
__device__ __forceinline__ void cpa16(uint32_t sm, const void* gm) {
    asm volatile("cp.async.cg.shared.global [%0], [%1], 16;"
        :: "r"(sm), "l"(__cvta_generic_to_global(gm)));
}
#define CP_COMMIT() asm volatile("cp.async.commit_group;" ::: "memory")
#define CP_WAIT0()  asm volatile("cp.async.wait_group 0;" ::: "memory")
#define CP_WAIT1()  asm volatile("cp.async.wait_group 1;" ::: "memory")

__device__ __forceinline__ void split_bf(float v, bf16& h, bf16& l) {
    h = __float2bfloat16_rn(v);
    l = __float2bfloat16_rn(v - __bfloat162float(h));
}

// ------------------- init / split kernels -------------------
__global__ void initX_k(const float4* __restrict__ v, const float4* __restrict__ m) {
    int i = blockIdx.x * 256 + threadIdx.x;
    float s = 0.f;
#pragma unroll
    for (int q = 0; q < 4; q++) {
        float4 vv = v[i * 4 + q], mm = m[i * 4 + q];
        s += fabsf(mm.x) + fabsf(mm.y) + fabsf(mm.z) + fabsf(mm.w);
        float4 x = make_float4(vv.x * mm.x, vv.y * mm.y, vv.z * mm.z, vv.w * mm.w);
        size_t o = (size_t)i * 16 + q * 4;
        split_bf(x.x, g_Xhi[o + 0], g_Xlo[o + 0]);
        split_bf(x.y, g_Xhi[o + 1], g_Xlo[o + 1]);
        split_bf(x.z, g_Xhi[o + 2], g_Xlo[o + 2]);
        split_bf(x.w, g_Xhi[o + 3], g_Xlo[o + 3]);
    }
    g_obs[i] = (s > 1e-4f) ? 1.f : 0.f;
}
__global__ void initS_k(const float* __restrict__ h0, const float* __restrict__ z0) {
    int i = blockIdx.x * 256 + threadIdx.x;
    int c = i & 127;
    float v = (c < 64) ? h0[c] : z0[c - 64];
    g_S[i] = v;
    split_bf(v, g_Shi[i], g_Slo[i]);
}
__global__ void splitA_k(const float* __restrict__ src, bf16* __restrict__ hi, bf16* __restrict__ lo) {
    size_t i = (size_t)blockIdx.x * 256 + threadIdx.x;
    split_bf(src[i], hi[i], lo[i]);
}
__global__ void splitW_k(const float* __restrict__ src, bf16* __restrict__ hi, bf16* __restrict__ lo,
                         int K, int N, int Npad) {
    int i = blockIdx.x * 256 + threadIdx.x;
    int k = i / Npad, n = i - k * Npad;
    float v = (k < K && n < N) ? src[k * N + n] : 0.f;
    split_bf(v, hi[i], lo[i]);
}

// ------------------- feature gather decode (GRU K=240 layout) -------------------
__device__ __forceinline__ const bf16* gru_feat(
    int kk, int Kdim, int grow, int z, int t, int arr,
    const bf16* __restrict__ Hhi, const bf16* __restrict__ Hlo)
{
    if (kk >= Kdim) return g_zero_bf;
    int bb = grow >> 10, n = grow & 1023;
    size_t xb = (((size_t)bb * TTi + t) * NNi + n) * 16;
    const bf16 *hi, *lo; size_t o2;
    if (kk < 16)       { hi = g_Xhi;   lo = g_Xlo;   o2 = xb + kk; }
    else if (kk < 80)  { hi = Hhi;     lo = Hlo;     o2 = (size_t)grow * 128 + z * 64 + (kk - 16); }
    else if (kk < 96)  { hi = g_AX1hi; lo = g_AX1lo; o2 = xb + (kk - 80); }
    else if (kk < 160) { hi = g_B1hi;  lo = g_B1lo;  o2 = (size_t)grow * 128 + z * 64 + (kk - 96); }
    else if (kk < 176) { hi = g_AX2hi; lo = g_AX2lo; o2 = xb + (kk - 160); }
    else               { hi = g_B2hi;  lo = g_B2lo;  o2 = (size_t)grow * 128 + z * 64 + (kk - 176); }
    return (arr ? lo : hi) + o2;
}

// ------------------- diffusion GEMM (64x128 tile, K=1024, 3-stage) -------------------
#define GP_STAGE  27648
#define A_LO_OFF  5120
#define B_OFF     10240
#define B_LO_OFF  8704

__device__ __forceinline__ void gp_load(
    uint32_t so, int k0, int row0, int col0, int bT,
    const bf16* __restrict__ Ah, const bf16* __restrict__ Al,
    const bf16* __restrict__ Bh, const bf16* __restrict__ Bl,
    int ldb, int bxmode)
{
    int t = threadIdx.x;
#pragma unroll
    for (int i = 0; i < 2; i++) {
        int c = t + i * 256;
        int arr = c >> 8, cc = c & 255, row = cc >> 2, seg = cc & 3;
        const bf16* g = (arr ? Al : Ah) + (size_t)(row0 + row) * NNi + k0 + seg * 8;
        cpa16(so + arr * A_LO_OFF + row * 80 + seg * 16, g);
    }
#pragma unroll
    for (int i = 0; i < 4; i++) {
        int c = t + i * 256;
        int arr = c >> 9, cc = c & 511, k = cc >> 4, seg = cc & 15;
        size_t off;
        if (bxmode) {
            int col = col0 + seg * 8;
            off = ((size_t)(bT + (col >> 4)) * NNi + (k0 + k)) * 16 + (col & 15);
        } else {
            off = (size_t)(k0 + k) * ldb + col0 + seg * 8;
        }
        cpa16(so + B_OFF + arr * B_LO_OFF + k * 272 + seg * 16, (arr ? Bl : Bh) + off);
    }
    CP_COMMIT();
}

__global__ void __launch_bounds__(256, 2) gemmP_hmma(
    const bf16* __restrict__ Ahi1, const bf16* __restrict__ Alo1,
    const bf16* __restrict__ Ahi2, const bf16* __restrict__ Alo2,
    const bf16* __restrict__ Bhi, const bf16* __restrict__ Blo,
    int ldb, size_t bstride, int bxmode,
    bf16* __restrict__ O1hi, bf16* __restrict__ O1lo,
    bf16* __restrict__ O2hi, bf16* __restrict__ O2lo,
    int ldo, size_t ostride, int oxmode)
{
    extern __shared__ char smraw[];
    int bz = blockIdx.z;
    int b = bz & 7, hop = bz >> 3;
    const bf16* Ah = (hop ? Ahi2 : Ahi1) + (size_t)b * NNi * NNi;
    const bf16* Al = (hop ? Alo2 : Alo1) + (size_t)b * NNi * NNi;
    const bf16* Bh = bxmode ? Bhi : Bhi + (size_t)b * bstride;
    const bf16* Bl = bxmode ? Blo : Blo + (size_t)b * bstride;
    bf16* Ohi = (hop ? O2hi : O1hi) + (oxmode ? 0 : (size_t)b * ostride);
    bf16* Olo = (hop ? O2lo : O1lo) + (oxmode ? 0 : (size_t)b * ostride);
    int row0 = blockIdx.x * 64, col0 = blockIdx.y * 128;
    int bT = b * TTi;

    int t = threadIdx.x, wid = t >> 5, lane = t & 31;
    int wm = (wid & 1) * 32, wn = (wid >> 1) * 32;
    uint32_t sbase = smem_u32(smraw);

    float acc[2][4][4];
#pragma unroll
    for (int mt = 0; mt < 2; mt++)
#pragma unroll
        for (int nt = 0; nt < 4; nt++)
#pragma unroll
            for (int q = 0; q < 4; q++) acc[mt][nt][q] = 0.f;

    uint32_t lmRow  = lane & 15;
    uint32_t lmColB = (lane >> 4) * 16;

    gp_load(sbase,            0,  row0, col0, bT, Ah, Al, Bh, Bl, ldb, bxmode);
    gp_load(sbase + GP_STAGE, 32, row0, col0, bT, Ah, Al, Bh, Bl, ldb, bxmode);

    int s0 = 0, s1 = 1, s2 = 2;
    for (int kt = 0; kt < 32; kt++) {
        if (kt < 31) { CP_WAIT1(); } else { CP_WAIT0(); }
        __syncthreads();
        if (kt + 2 < 32)
            gp_load(sbase + (uint32_t)s2 * GP_STAGE, (kt + 2) * 32, row0, col0, bT,
                    Ah, Al, Bh, Bl, ldb, bxmode);

        uint32_t so = sbase + (uint32_t)s0 * GP_STAGE;
#pragma unroll
        for (int ks = 0; ks < 2; ks++) {
            uint32_t ah[2][4], al[2][4];
#pragma unroll
            for (int mt = 0; mt < 2; mt++) {
                uint32_t ad = so + (wm + mt * 16 + lmRow) * 80 + ks * 32 + lmColB;
                ldm4(ah[mt], ad);
                ldm4(al[mt], ad + A_LO_OFF);
            }
#pragma unroll
            for (int np = 0; np < 2; np++) {
                uint32_t bd = so + B_OFF + (ks * 16 + lmRow) * 272 + (wn + np * 16) * 2 + lmColB;
                uint32_t bh[4], bl[4];
                ldm4t(bh, bd);
                ldm4t(bl, bd + B_LO_OFF);
#pragma unroll
                for (int mt = 0; mt < 2; mt++) {
                    mma_bf(acc[mt][2 * np],     ah[mt], bh[0], bh[1]);
                    mma_bf(acc[mt][2 * np + 1], ah[mt], bh[2], bh[3]);
                    mma_bf(acc[mt][2 * np],     ah[mt], bl[0], bl[1]);
                    mma_bf(acc[mt][2 * np + 1], ah[mt], bl[2], bl[3]);
                    mma_bf(acc[mt][2 * np],     al[mt], bh[0], bh[1]);
                    mma_bf(acc[mt][2 * np + 1], al[mt], bh[2], bh[3]);
                }
            }
        }
        int sx = s0; s0 = s1; s1 = s2; s2 = sx;
    }

    int gr = lane >> 2, gc = (lane & 3) * 2;
#pragma unroll
    for (int mt = 0; mt < 2; mt++)
#pragma unroll
        for (int nt = 0; nt < 4; nt++) {
            int r = row0 + wm + mt * 16 + gr;
            int c = col0 + wn + nt * 8 + gc;
#pragma unroll
            for (int half = 0; half < 2; half++) {
                int rr = r + half * 8;
                bf16 h0, l0, h1, l1;
                split_bf(acc[mt][nt][half * 2 + 0], h0, l0);
                split_bf(acc[mt][nt][half * 2 + 1], h1, l1);
                size_t off;
                if (oxmode) off = ((size_t)(bT + (c >> 4)) * NNi + rr) * 16 + (c & 15);
                else        off = (size_t)rr * ldo + c;
                *(__nv_bfloat162*)&Ohi[off] = __halves2bfloat162(h0, h1);
                *(__nv_bfloat162*)&Olo[off] = __halves2bfloat162(l0, l1);
            }
        }
}

// ------------------- epilogue helpers -------------------
__device__ __forceinline__ void dh_epi(int mode, int z, int t, int row, int col, float v) {
    if (mode == 2) {
        float g = 1.f / (1.f + expf(-v));
        if (col < 64) {
            size_t ii = (size_t)row * 128 + z * 64 + col;
            float rh = g * g_S[ii];
            split_bf(rh, g_RHhi[ii], g_RHlo[ii]);
        } else {
            g_u[(size_t)row * 128 + z * 64 + (col - 64)] = g;
        }
    } else { // 3
        float cc = tanhf(v);
        size_t ii = (size_t)row * 128 + z * 64 + col;
        float u = g_u[ii], h = g_S[ii];
        float m = g_obs[((size_t)(row >> 10) * TTi + t) * NNi + (row & 1023)];
        float hn = u * h + (1.f - u) * cc;
        float s = h + m * (hn - h);
        g_S[ii] = s;
        split_bf(s, g_Shi[ii], g_Slo[ii]);
    }
}

// ------------------- GRU gate dense: 64x128 tile (gemm-shaped) -------------------
__device__ __forceinline__ void dg_load(
    uint32_t so, int k0, int row0, int z, int t,
    const bf16* __restrict__ Hhi, const bf16* __restrict__ Hlo,
    const bf16* __restrict__ Whi, const bf16* __restrict__ Wlo)
{
    int tid = threadIdx.x;
#pragma unroll
    for (int i = 0; i < 2; i++) {          // A: 64 rows x 32 k, hi+lo
        int c = tid + i * 256;
        int arr = c >> 8, cc = c & 255, row = cc >> 2, seg = cc & 3;
        int kk = k0 + seg * 8;
        cpa16(so + arr * A_LO_OFF + row * 80 + seg * 16,
              gru_feat(kk, 240, row0 + row, z, t, arr, Hhi, Hlo));
    }
#pragma unroll
    for (int i = 0; i < 4; i++) {          // B(Wg): 32 k x 128 cols, hi+lo
        int c = tid + i * 256;
        int arr = c >> 9, cc = c & 511, k = cc >> 4, seg = cc & 15;
        const bf16* w = (arr ? Wlo : Whi) + (size_t)(k0 + k) * 128 + seg * 8;
        cpa16(so + B_OFF + arr * B_LO_OFF + k * 272 + seg * 16, w);
    }
    CP_COMMIT();
}

__global__ void __launch_bounds__(256, 2) denseG_k(
    int t,
    const bf16* __restrict__ Hhi, const bf16* __restrict__ Hlo,
    const bf16* __restrict__ W0hi, const bf16* __restrict__ W0lo,
    const bf16* __restrict__ W1hi, const bf16* __restrict__ W1lo,
    const float* __restrict__ bias0, const float* __restrict__ bias1)
{
    extern __shared__ char smraw[];
    int z = blockIdx.z;
    int row0 = blockIdx.x * 64;
    const bf16* Whi = z ? W1hi : W0hi;
    const bf16* Wlo = z ? W1lo : W0lo;
    const float* bias = z ? bias1 : bias0;

    int tid = threadIdx.x, wid = tid >> 5, lane = tid & 31;
    int wm = (wid & 1) * 32, wn = (wid >> 1) * 32;
    uint32_t sbase = smem_u32(smraw);
    uint32_t lmRow = lane & 15, lmColB = (lane >> 4) * 16;

    float acc[2][4][4];
#pragma unroll
    for (int mt = 0; mt < 2; mt++)
#pragma unroll
        for (int nt = 0; nt < 4; nt++)
#pragma unroll
            for (int q = 0; q < 4; q++) acc[mt][nt][q] = 0.f;

    dg_load(sbase,            0,  row0, z, t, Hhi, Hlo, Whi, Wlo);
    dg_load(sbase + GP_STAGE, 32, row0, z, t, Hhi, Hlo, Whi, Wlo);

    for (int kt = 0; kt < 8; kt++) {
        if (kt < 7) { CP_WAIT1(); } else { CP_WAIT0(); }
        __syncthreads();

        uint32_t so = sbase + (uint32_t)(kt & 1) * GP_STAGE;
#pragma unroll
        for (int ks = 0; ks < 2; ks++) {
            uint32_t ah[2][4], al[2][4];
#pragma unroll
            for (int mt = 0; mt < 2; mt++) {
                uint32_t ad = so + (wm + mt * 16 + lmRow) * 80 + ks * 32 + lmColB;
                ldm4(ah[mt], ad);
                ldm4(al[mt], ad + A_LO_OFF);
            }
#pragma unroll
            for (int np = 0; np < 2; np++) {
                uint32_t bd = so + B_OFF + (ks * 16 + lmRow) * 272 + (wn + np * 16) * 2 + lmColB;
                uint32_t bh[4], bl[4];
                ldm4t(bh, bd);
                ldm4t(bl, bd + B_LO_OFF);
#pragma unroll
                for (int mt = 0; mt < 2; mt++) {
                    mma_bf(acc[mt][2 * np],     ah[mt], bh[0], bh[1]);
                    mma_bf(acc[mt][2 * np + 1], ah[mt], bh[2], bh[3]);
                    mma_bf(acc[mt][2 * np],     ah[mt], bl[0], bl[1]);
                    mma_bf(acc[mt][2 * np + 1], ah[mt], bl[2], bl[3]);
                    mma_bf(acc[mt][2 * np],     al[mt], bh[0], bh[1]);
                    mma_bf(acc[mt][2 * np + 1], al[mt], bh[2], bh[3]);
                }
            }
        }
        __syncthreads();
        if (kt + 2 < 8)
            dg_load(sbase + (uint32_t)(kt & 1) * GP_STAGE, (kt + 2) * 32, row0, z, t,
                    Hhi, Hlo, Whi, Wlo);
    }

    int gr = lane >> 2, gc = (lane & 3) * 2;
#pragma unroll
    for (int mt = 0; mt < 2; mt++)
#pragma unroll
        for (int nt = 0; nt < 4; nt++) {
            int r = row0 + wm + mt * 16 + gr;
            int c = wn + nt * 8 + gc;
            dh_epi(2, z, t, r,     c,     acc[mt][nt][0] + bias[c]);
            dh_epi(2, z, t, r,     c + 1, acc[mt][nt][1] + bias[c + 1]);
            dh_epi(2, z, t, r + 8, c,     acc[mt][nt][2] + bias[c]);
            dh_epi(2, z, t, r + 8, c + 1, acc[mt][nt][3] + bias[c + 1]);
        }
}

// ------------------- dense HMMA (M=128 tiles, GRU cand) -------------------
#define DH_A_STRIDE 80
#define DH_ALO_OFF  10240
#define DH_B_OFF    20480
#define DH_B_STRIDE 144
#define DH_BLO_OFF  4608
#define DH_STAGE    29696

__device__ __forceinline__ void dh_load_stage(
    uint32_t so, int k0, int row0, int z, int t, int col0, int Kdim,
    const bf16* __restrict__ Hhi, const bf16* __restrict__ Hlo,
    const bf16* __restrict__ Whi, const bf16* __restrict__ Wlo, int Npad)
{
#pragma unroll
    for (int i = 0; i < 4; i++) {
        int c = threadIdx.x + i * 256;
        int arr = c >> 9, cc = c & 511;
        int row = cc >> 2, seg = cc & 3;
        int kk = k0 + seg * 8;
        cpa16(so + arr * DH_ALO_OFF + row * DH_A_STRIDE + seg * 16,
              gru_feat(kk, Kdim, row0 + row, z, t, arr, Hhi, Hlo));
    }
#pragma unroll
    for (int i = 0; i < 2; i++) {
        int c = threadIdx.x + i * 256;
        int arr = c >> 8, cc = c & 255;
        int k = cc >> 3, seg = cc & 7;
        const bf16* w = (arr ? Wlo : Whi) + (size_t)(k0 + k) * Npad + col0 + seg * 8;
        cpa16(so + DH_B_OFF + arr * DH_BLO_OFF + k * DH_B_STRIDE + seg * 16, w);
    }
    CP_COMMIT();
}

__global__ void __launch_bounds__(256, 2) denseH_k(
    int Kdim, int nkt, int mode, int t,
    const bf16* __restrict__ Hhi, const bf16* __restrict__ Hlo,
    const bf16* __restrict__ W0hi, const bf16* __restrict__ W0lo,
    const bf16* __restrict__ W1hi, const bf16* __restrict__ W1lo, int Npad,
    const float* __restrict__ bias0, const float* __restrict__ bias1)
{
    extern __shared__ char smraw[];
    int z = blockIdx.z;
    int row0 = blockIdx.x * 128;
    int col0 = blockIdx.y * 64;
    const bf16* Whi = z ? W1hi : W0hi;
    const bf16* Wlo = z ? W1lo : W0lo;
    const float* bias = z ? bias1 : bias0;

    int tid = threadIdx.x, wid = tid >> 5, lane = tid & 31;
    int wm = (wid & 3) * 32, wn = (wid >> 2) * 32;
    uint32_t sb = smem_u32(smraw);
    uint32_t lmRow = lane & 15, lmColB = (lane >> 4) * 16;

    float acc[2][4][4];
#pragma unroll
    for (int mt = 0; mt < 2; mt++)
#pragma unroll
        for (int nt = 0; nt < 4; nt++)
#pragma unroll
            for (int q = 0; q < 4; q++) acc[mt][nt][q] = 0.f;

    dh_load_stage(sb, 0, row0, z, t, col0, Kdim, Hhi, Hlo, Whi, Wlo, Npad);

    for (int kt = 0; kt < nkt; kt++) {
        if (kt + 1 < nkt)
            dh_load_stage(sb + ((kt + 1) & 1) * DH_STAGE, (kt + 1) * 32, row0, z, t, col0,
                          Kdim, Hhi, Hlo, Whi, Wlo, Npad);
        if (kt + 1 < nkt) { CP_WAIT1(); } else { CP_WAIT0(); }
        __syncthreads();

        uint32_t so = sb + (kt & 1) * DH_STAGE;
#pragma unroll
        for (int ks = 0; ks < 2; ks++) {
            uint32_t ah[2][4], al[2][4];
#pragma unroll
            for (int mt = 0; mt < 2; mt++) {
                uint32_t ad = so + (wm + mt * 16 + lmRow) * DH_A_STRIDE + ks * 32 + lmColB;
                ldm4(ah[mt], ad);
                ldm4(al[mt], ad + DH_ALO_OFF);
            }
#pragma unroll
            for (int np = 0; np < 2; np++) {
                uint32_t bd = so + DH_B_OFF + (ks * 16 + lmRow) * DH_B_STRIDE + (wn + np * 16) * 2 + lmColB;
                uint32_t bh[4], bl[4];
                ldm4t(bh, bd);
                ldm4t(bl, bd + DH_BLO_OFF);
#pragma unroll
                for (int mt = 0; mt < 2; mt++) {
                    mma_bf(acc[mt][2 * np],     ah[mt], bh[0], bh[1]);
                    mma_bf(acc[mt][2 * np + 1], ah[mt], bh[2], bh[3]);
                    mma_bf(acc[mt][2 * np],     ah[mt], bl[0], bl[1]);
                    mma_bf(acc[mt][2 * np + 1], ah[mt], bl[2], bl[3]);
                    mma_bf(acc[mt][2 * np],     al[mt], bh[0], bh[1]);
                    mma_bf(acc[mt][2 * np + 1], al[mt], bh[2], bh[3]);
                }
            }
        }
        __syncthreads();
    }

    int gr = lane >> 2, gc = (lane & 3) * 2;
#pragma unroll
    for (int mt = 0; mt < 2; mt++)
#pragma unroll
        for (int nt = 0; nt < 4; nt++) {
            int r = row0 + wm + mt * 16 + gr;
            int c = col0 + wn + nt * 8 + gc;
            dh_epi(mode, z, t, r,     c,     acc[mt][nt][0] + bias[c]);
            dh_epi(mode, z, t, r,     c + 1, acc[mt][nt][1] + bias[c + 1]);
            dh_epi(mode, z, t, r + 8, c,     acc[mt][nt][2] + bias[c]);
            dh_epi(mode, z, t, r + 8, c + 1, acc[mt][nt][3] + bias[c + 1]);
        }
}

// ------------------- fused ODE step, 64-row tiles -------------------
#define OD_ALO   5120
#define OD_B     10240
#define OD_BLO   4608
#define OD_STAGE 19456
#define OD_H1HI  38912
#define OD_H1LO  48128
#define OD_SMEM  57344

__device__ __forceinline__ void ode_load64(
    uint32_t so, int k0, int row0, int z,
    const bf16* __restrict__ Whi, const bf16* __restrict__ Wlo)
{
#pragma unroll
    for (int i = 0; i < 2; i++) {
        int c = threadIdx.x + i * 256;
        int arr = c >> 8, cc = c & 255;
        int row = cc >> 2, seg = cc & 3;
        int kk = k0 + seg * 8;
        int grow = row0 + row;
        const bf16 *hi, *lo; int kloc;
        if (kk < 64)       { hi = g_Shi;  lo = g_Slo;  kloc = kk; }
        else if (kk < 128) { hi = g_B1hi; lo = g_B1lo; kloc = kk - 64; }
        else               { hi = g_B2hi; lo = g_B2lo; kloc = kk - 128; }
        const bf16* src = arr ? lo : hi;
        size_t off = (size_t)grow * 128 + z * 64 + kloc;
        cpa16(so + arr * OD_ALO + row * 80 + seg * 16, src + off);
    }
#pragma unroll
    for (int i = 0; i < 2; i++) {
        int c = threadIdx.x + i * 256;
        int arr = c >> 8, cc = c & 255;
        int k = cc >> 3, seg = cc & 7;
        const bf16* w = (arr ? Wlo : Whi) + (size_t)(k0 + k) * 64 + seg * 8;
        cpa16(so + OD_B + arr * OD_BLO + k * 144 + seg * 16, w);
    }
    CP_COMMIT();
}

__global__ void __launch_bounds__(256, 2) denseODE_k(
    int t_pre,
    const bf16* __restrict__ W0hi, const bf16* __restrict__ W0lo,
    const bf16* __restrict__ Wouthi, const bf16* __restrict__ Woutlo,
    const float* __restrict__ b0_0, const float* __restrict__ b0_1,
    const float* __restrict__ bo_0, const float* __restrict__ bo_1)
{
    extern __shared__ char smraw[];
    int z = blockIdx.z;
    int row0 = blockIdx.x * 64;
    const bf16* Whi = W0hi + (size_t)z * 12288;
    const bf16* Wlo = W0lo + (size_t)z * 12288;
    const bf16* WoH = Wouthi + (size_t)z * 4096;
    const bf16* WoL = Woutlo + (size_t)z * 4096;
    const float* b0 = z ? b0_1 : b0_0;
    const float* bo = z ? bo_1 : bo_0;

    int tid = threadIdx.x, wid = tid >> 5, lane = tid & 31;
    int wm = (wid & 3) * 16, wn = (wid >> 2) * 32;
    uint32_t sb = smem_u32(smraw);
    uint32_t lmRow = lane & 15, lmColB = (lane >> 4) * 16;
    int gr = lane >> 2, gc = (lane & 3) * 2;

    float acc[4][4];
#pragma unroll
    for (int nt = 0; nt < 4; nt++)
#pragma unroll
        for (int q = 0; q < 4; q++) acc[nt][q] = 0.f;

    ode_load64(sb, 0, row0, z, Whi, Wlo);
    for (int kt = 0; kt < 6; kt++) {
        if (kt < 5)
            ode_load64(sb + ((kt + 1) & 1) * OD_STAGE, (kt + 1) * 32, row0, z, Whi, Wlo);
        if (kt < 5) { CP_WAIT1(); } else { CP_WAIT0(); }
        __syncthreads();
        uint32_t so = sb + (kt & 1) * OD_STAGE;
#pragma unroll
        for (int ks = 0; ks < 2; ks++) {
            uint32_t ah[4], al[4];
            uint32_t ad = so + (wm + lmRow) * 80 + ks * 32 + lmColB;
            ldm4(ah, ad);
            ldm4(al, ad + OD_ALO);
#pragma unroll
            for (int np = 0; np < 2; np++) {
                uint32_t bd = so + OD_B + (ks * 16 + lmRow) * 144 + (wn + np * 16) * 2 + lmColB;
                uint32_t bh[4], bl[4];
                ldm4t(bh, bd);
                ldm4t(bl, bd + OD_BLO);
                mma_bf(acc[2 * np],     ah, bh[0], bh[1]);
                mma_bf(acc[2 * np + 1], ah, bh[2], bh[3]);
                mma_bf(acc[2 * np],     ah, bl[0], bl[1]);
                mma_bf(acc[2 * np + 1], ah, bl[2], bl[3]);
                mma_bf(acc[2 * np],     al, bh[0], bh[1]);
                mma_bf(acc[2 * np + 1], al, bh[2], bh[3]);
            }
        }
        __syncthreads();
    }

#pragma unroll
    for (int nt = 0; nt < 4; nt++) {
        int rl = wm + gr;
        int c = wn + nt * 8 + gc;
        float v0 = tanhf(acc[nt][0] + b0[c]);
        float v1 = tanhf(acc[nt][1] + b0[c + 1]);
        float v2 = tanhf(acc[nt][2] + b0[c]);
        float v3 = tanhf(acc[nt][3] + b0[c + 1]);
        bf16 h0, l0, h1, l1;
        split_bf(v0, h0, l0); split_bf(v1, h1, l1);
        *(__nv_bfloat162*)(smraw + OD_H1HI + rl * 144 + c * 2) = __halves2bfloat162(h0, h1);
        *(__nv_bfloat162*)(smraw + OD_H1LO + rl * 144 + c * 2) = __halves2bfloat162(l0, l1);
        split_bf(v2, h0, l0); split_bf(v3, h1, l1);
        *(__nv_bfloat162*)(smraw + OD_H1HI + (rl + 8) * 144 + c * 2) = __halves2bfloat162(h0, h1);
        *(__nv_bfloat162*)(smraw + OD_H1LO + (rl + 8) * 144 + c * 2) = __halves2bfloat162(l0, l1);
    }
    __syncthreads();

#pragma unroll
    for (int i = 0; i < 4; i++) {
        int c = tid + i * 256;
        int arr = c >> 9, cc = c & 511, k = cc >> 3, seg = cc & 7;
        *(uint4*)(smraw + arr * 9216 + k * 144 + seg * 16) =
            *(const uint4*)((arr ? WoL : WoH) + (size_t)k * 64 + seg * 8);
    }
    __syncthreads();

#pragma unroll
    for (int nt = 0; nt < 4; nt++)
#pragma unroll
        for (int q = 0; q < 4; q++) acc[nt][q] = 0.f;

#pragma unroll
    for (int ks = 0; ks < 4; ks++) {
        uint32_t ah[4], al[4];
        uint32_t ad = sb + OD_H1HI + (wm + lmRow) * 144 + ks * 32 + lmColB;
        ldm4(ah, ad);
        ldm4(al, ad + (OD_H1LO - OD_H1HI));
#pragma unroll
        for (int np = 0; np < 2; np++) {
            uint32_t bd = sb + (ks * 16 + lmRow) * 144 + (wn + np * 16) * 2 + lmColB;
            uint32_t bh[4], bl[4];
            ldm4t(bh, bd);
            ldm4t(bl, bd + 9216);
            mma_bf(acc[2 * np],     ah, bh[0], bh[1]);
            mma_bf(acc[2 * np + 1], ah, bh[2], bh[3]);
            mma_bf(acc[2 * np],     ah, bl[0], bl[1]);
            mma_bf(acc[2 * np + 1], ah, bl[2], bl[3]);
            mma_bf(acc[2 * np],     al, bh[0], bh[1]);
            mma_bf(acc[2 * np + 1], al, bh[2], bh[3]);
        }
    }

#pragma unroll
    for (int nt = 0; nt < 4; nt++) {
        int r = row0 + wm + gr;
        int c = wn + nt * 8 + gc;
#pragma unroll
        for (int q = 0; q < 4; q++) {
            int rr = r + (q >> 1) * 8;
            int cc = c + (q & 1);
            size_t ii = (size_t)rr * 128 + z * 64 + cc;
            float s = g_S[ii] + DT_SUB * tanhf(acc[nt][q] + bo[cc]);
            g_S[ii] = s;
            split_bf(s, g_Shi[ii], g_Slo[ii]);
            if (t_pre >= 1) {
                if (z == 0) {
                    g_pre[(size_t)t_pre * ((size_t)ROWSi * 128) + ii] = s;
                } else {
                    size_t pz = ((size_t)(t_pre - 1) * ROWSi + rr) * 64 + cc;
                    split_bf(s, g_preZhi[pz], g_preZlo[pz]);
                }
            }
        }
    }
}

// ------------------- fused output head -------------------
#define HF_A    0
#define HF_ALO  9216
#define HF_W    18432
#define HF_WLO  27648
#define HF_T    36864
#define HF_TLO  46080
#define HF_HVP  55296
#define HF_SMEM 71680

__device__ __forceinline__ void hf_gemm(
    uint32_t sb, uint32_t aOff, uint32_t aLoDelta, float acc[4][4],
    int wm, int wn, uint32_t lmRow, uint32_t lmColB)
{
#pragma unroll
    for (int nt = 0; nt < 4; nt++)
#pragma unroll
        for (int q = 0; q < 4; q++) acc[nt][q] = 0.f;
#pragma unroll
    for (int ks = 0; ks < 4; ks++) {
        uint32_t ah[4], al[4];
        uint32_t ad = sb + aOff + (wm + lmRow) * 144 + ks * 32 + lmColB;
        ldm4(ah, ad);
        ldm4(al, ad + aLoDelta);
#pragma unroll
        for (int np = 0; np < 2; np++) {
            uint32_t bd = sb + HF_W + (ks * 16 + lmRow) * 144 + (wn + np * 16) * 2 + lmColB;
            uint32_t bh[4], bl[4];
            ldm4t(bh, bd);
            ldm4t(bl, bd + 9216);
            mma_bf(acc[2 * np],     ah, bh[0], bh[1]);
            mma_bf(acc[2 * np + 1], ah, bh[2], bh[3]);
            mma_bf(acc[2 * np],     ah, bl[0], bl[1]);
            mma_bf(acc[2 * np + 1], ah, bl[2], bl[3]);
            mma_bf(acc[2 * np],     al, bh[0], bh[1]);
            mma_bf(acc[2 * np + 1], al, bh[2], bh[3]);
        }
    }
}

__device__ __forceinline__ void hf_wcopy(char* smraw, int tid, const bf16* Whi, const bf16* Wlo) {
#pragma unroll
    for (int i = 0; i < 4; i++) {
        int c = tid + i * 256;
        int arr = c >> 9, cc = c & 511, k = cc >> 3, seg = cc & 7;
        *(uint4*)(smraw + HF_W + arr * 9216 + k * 144 + seg * 16) =
            *(const uint4*)((arr ? Wlo : Whi) + (size_t)k * 64 + seg * 8);
    }
}

__global__ void __launch_bounds__(256, 2) headF_k(
    const float* __restrict__ bz1, const float* __restrict__ bz2,
    const float* __restrict__ bz3, const float* __restrict__ boo,
    float* __restrict__ out4)
{
    extern __shared__ char smraw[];
    int row0 = blockIdx.x * 64;
    int tid = threadIdx.x, wid = tid >> 5, lane = tid & 31;
    int wm = (wid & 3) * 16, wn = (wid >> 2) * 32;
    uint32_t sb = smem_u32(smraw);
    uint32_t lmRow = lane & 15, lmColB = (lane >> 4) * 16;
    int gr = lane >> 2, gc = (lane & 3) * 2;

#pragma unroll
    for (int i = 0; i < 4; i++) {
        int c = tid + i * 256;
        int arr = c >> 9, cc = c & 511, row = cc >> 3, seg = cc & 7;
        const bf16* src = (arr ? g_preZlo : g_preZhi) + (size_t)(row0 + row) * 64 + seg * 8;
        cpa16(sb + HF_A + arr * 9216 + row * 144 + seg * 16, src);
    }
#pragma unroll
    for (int i = 0; i < 4; i++) {
        int c = tid + i * 256;
        int arr = c >> 9, cc = c & 511, k = cc >> 3, seg = cc & 7;
        const bf16* w = (arr ? g_hWlo : g_hWhi) + (size_t)k * 64 + seg * 8;
        cpa16(sb + HF_W + arr * 9216 + k * 144 + seg * 16, w);
    }
#pragma unroll
    for (int i = 0; i < 4; i++) {
        int c = tid + i * 256;
        int row = c >> 4, seg = c & 15;
        const float* src = &g_pre[(size_t)(row0 + row + ROWSi) * 128 + seg * 4];
        cpa16(sb + HF_HVP + row * 256 + seg * 16, src);
    }
    CP_COMMIT();
    CP_WAIT0();
    __syncthreads();

    float acc[4][4];
    hf_gemm(sb, HF_A, 9216, acc, wm, wn, lmRow, lmColB);
#pragma unroll
    for (int nt = 0; nt < 4; nt++) {
        int rl = wm + gr;
        int c = wn + nt * 8 + gc;
        float v0 = tanhf(acc[nt][0] + bz1[c]);
        float v1 = tanhf(acc[nt][1] + bz1[c + 1]);
        float v2 = tanhf(acc[nt][2] + bz1[c]);
        float v3 = tanhf(acc[nt][3] + bz1[c + 1]);
        bf16 h0, l0, h1, l1;
        split_bf(v0, h0, l0); split_bf(v1, h1, l1);
        *(__nv_bfloat162*)(smraw + HF_T   + rl * 144 + c * 2) = __halves2bfloat162(h0, h1);
        *(__nv_bfloat162*)(smraw + HF_TLO + rl * 144 + c * 2) = __halves2bfloat162(l0, l1);
        split_bf(v2, h0, l0); split_bf(v3, h1, l1);
        *(__nv_bfloat162*)(smraw + HF_T   + (rl + 8) * 144 + c * 2) = __halves2bfloat162(h0, h1);
        *(__nv_bfloat162*)(smraw + HF_TLO + (rl + 8) * 144 + c * 2) = __halves2bfloat162(l0, l1);
    }
    __syncthreads();

    hf_wcopy(smraw, tid, g_hWhi + 4096, g_hWlo + 4096);
    __syncthreads();
    hf_gemm(sb, HF_T, 9216, acc, wm, wn, lmRow, lmColB);
#pragma unroll
    for (int nt = 0; nt < 4; nt++) {
        int rl = wm + gr;
        int c = wn + nt * 8 + gc;
        float v0 = tanhf(acc[nt][0] + bz2[c]);
        float v1 = tanhf(acc[nt][1] + bz2[c + 1]);
        float v2 = tanhf(acc[nt][2] + bz2[c]);
        float v3 = tanhf(acc[nt][3] + bz2[c + 1]);
        bf16 h0, l0, h1, l1;
        split_bf(v0, h0, l0); split_bf(v1, h1, l1);
        *(__nv_bfloat162*)(smraw + HF_A   + rl * 144 + c * 2) = __halves2bfloat162(h0, h1);
        *(__nv_bfloat162*)(smraw + HF_ALO + rl * 144 + c * 2) = __halves2bfloat162(l0, l1);
        split_bf(v2, h0, l0); split_bf(v3, h1, l1);
        *(__nv_bfloat162*)(smraw + HF_A   + (rl + 8) * 144 + c * 2) = __halves2bfloat162(h0, h1);
        *(__nv_bfloat162*)(smraw + HF_ALO + (rl + 8) * 144 + c * 2) = __halves2bfloat162(l0, l1);
    }
    __syncthreads();

    hf_wcopy(smraw, tid, g_hWhi + 8192, g_hWlo + 8192);
    __syncthreads();
    hf_gemm(sb, HF_A, 9216, acc, wm, wn, lmRow, lmColB);
#pragma unroll
    for (int nt = 0; nt < 4; nt++) {
        int rl = wm + gr;
        int c = wn + nt * 8 + gc;
#pragma unroll
        for (int q = 0; q < 4; q++) {
            int rrl = rl + (q >> 1) * 8;
            int cc = c + (q & 1);
            float g = 1.f / (1.f + expf(-(acc[nt][q] + bz3[cc])));
            float v = g * *(const float*)(smraw + HF_HVP + rrl * 256 + cc * 4);
            bf16 h0, l0;
            split_bf(v, h0, l0);
            *(bf16*)(smraw + HF_T   + rrl * 144 + cc * 2) = h0;
            *(bf16*)(smraw + HF_TLO + rrl * 144 + cc * 2) = l0;
        }
    }
    __syncthreads();

    hf_wcopy(smraw, tid, g_hWhi + 12288, g_hWlo + 12288);
    __syncthreads();
    hf_gemm(sb, HF_T, 9216, acc, wm, wn, lmRow, lmColB);
#pragma unroll
    for (int nt = 0; nt < 4; nt++) {
        int c = wn + nt * 8 + gc;
#pragma unroll
        for (int q = 0; q < 4; q++) {
            int cc = c + (q & 1);
            if (cc >= 16) continue;
            int rr = row0 + wm + gr + (q >> 1) * 8;
            int tp = rr >> 13, bn = rr & 8191;
            int bb = bn >> 10, n = bn & 1023;
            out4[(((size_t)bb * 39 + tp) * NNi + n) * 16 + cc] = acc[nt][q] + boo[cc];
        }
    }
}

// ------------------- host orchestration -------------------
extern "C" void kernel_launch(void* const* d_in, const int* in_sizes, int n_in,
                              void* d_out, int out_size) {
    const float* values  = (const float*)d_in[0];
    const float* masks   = (const float*)d_in[1];
    const float* A       = (const float*)d_in[2];
    const float* h0      = (const float*)d_in[3];
    const float* z0      = (const float*)d_in[4];
    const float* gV_Wg   = (const float*)d_in[5];
    const float* gV_bg   = (const float*)d_in[6];
    const float* gV_Wc   = (const float*)d_in[7];
    const float* gV_bc   = (const float*)d_in[8];
    const float* gG_Wg   = (const float*)d_in[9];
    const float* gG_bg   = (const float*)d_in[10];
    const float* gG_Wc   = (const float*)d_in[11];
    const float* gG_bc   = (const float*)d_in[12];
    const float* oV_W0   = (const float*)d_in[13];
    const float* oV_b0   = (const float*)d_in[14];
    const float* oV_Wout = (const float*)d_in[15];
    const float* oV_bout = (const float*)d_in[16];
    const float* oG_W0   = (const float*)d_in[17];
    const float* oG_b0   = (const float*)d_in[18];
    const float* oG_Wout = (const float*)d_in[19];
    const float* oG_bout = (const float*)d_in[20];
    const float* Wz1     = (const float*)d_in[21];
    const float* bz1     = (const float*)d_in[22];
    const float* Wz2     = (const float*)d_in[23];
    const float* bz2     = (const float*)d_in[24];
    const float* Wz3     = (const float*)d_in[25];
    const float* bz3     = (const float*)d_in[26];
    const float* Wo      = (const float*)d_in[27];
    const float* bo      = (const float*)d_in[28];

    bf16 *pAhi, *pAlo, *pA2hi, *pA2lo, *pShi, *pSlo, *pRHhi, *pRHlo;
    bf16 *pB1hi, *pB1lo, *pB2hi, *pB2lo, *pXhi, *pXlo;
    bf16 *pAX1hi, *pAX1lo, *pAX2hi, *pAX2lo;
    bf16 *pOW0hi, *pOW0lo, *pOWouthi, *pOWoutlo, *pGWghi, *pGWglo, *pGWchi, *pGWclo;
    bf16 *pHWhi, *pHWlo;
    cudaGetSymbolAddress((void**)&pAhi,  g_Ahi);
    cudaGetSymbolAddress((void**)&pAlo,  g_Alo);
    cudaGetSymbolAddress((void**)&pA2hi, g_A2hi);
    cudaGetSymbolAddress((void**)&pA2lo, g_A2lo);
    cudaGetSymbolAddress((void**)&pShi,  g_Shi);
    cudaGetSymbolAddress((void**)&pSlo,  g_Slo);
    cudaGetSymbolAddress((void**)&pRHhi, g_RHhi);
    cudaGetSymbolAddress((void**)&pRHlo, g_RHlo);
    cudaGetSymbolAddress((void**)&pB1hi, g_B1hi);
    cudaGetSymbolAddress((void**)&pB1lo, g_B1lo);
    cudaGetSymbolAddress((void**)&pB2hi, g_B2hi);
    cudaGetSymbolAddress((void**)&pB2lo, g_B2lo);
    cudaGetSymbolAddress((void**)&pXhi,  g_Xhi);
    cudaGetSymbolAddress((void**)&pXlo,  g_Xlo);
    cudaGetSymbolAddress((void**)&pAX1hi, g_AX1hi);
    cudaGetSymbolAddress((void**)&pAX1lo, g_AX1lo);
    cudaGetSymbolAddress((void**)&pAX2hi, g_AX2hi);
    cudaGetSymbolAddress((void**)&pAX2lo, g_AX2lo);
    cudaGetSymbolAddress((void**)&pOW0hi,   g_oW0hi);
    cudaGetSymbolAddress((void**)&pOW0lo,   g_oW0lo);
    cudaGetSymbolAddress((void**)&pOWouthi, g_oWouthi);
    cudaGetSymbolAddress((void**)&pOWoutlo, g_oWoutlo);
    cudaGetSymbolAddress((void**)&pGWghi,   g_gWghi);
    cudaGetSymbolAddress((void**)&pGWglo,   g_gWglo);
    cudaGetSymbolAddress((void**)&pGWchi,   g_gWchi);
    cudaGetSymbolAddress((void**)&pGWclo,   g_gWclo);
    cudaGetSymbolAddress((void**)&pHWhi,    g_hWhi);
    cudaGetSymbolAddress((void**)&pHWlo,    g_hWlo);

    const int GP3 = 3 * GP_STAGE;            // 82944
    const int DH_SMEM = 2 * DH_STAGE;        // 59392
    const int DG_SMEM = 2 * GP_STAGE;        // 55296
    cudaFuncSetAttribute(gemmP_hmma, cudaFuncAttributeMaxDynamicSharedMemorySize, GP3);
    cudaFuncSetAttribute(denseH_k,   cudaFuncAttributeMaxDynamicSharedMemorySize, DH_SMEM);
    cudaFuncSetAttribute(denseG_k,   cudaFuncAttributeMaxDynamicSharedMemorySize, DG_SMEM);
    cudaFuncSetAttribute(denseODE_k, cudaFuncAttributeMaxDynamicSharedMemorySize, OD_SMEM);
    cudaFuncSetAttribute(headF_k,    cudaFuncAttributeMaxDynamicSharedMemorySize, HF_SMEM);

    const size_t sAA = (size_t)NNi * NNi;
    const size_t sS  = (size_t)NNi * 128;

    initX_k<<<1280, 256>>>((const float4*)values, (const float4*)masks);            // 0
    initS_k<<<4096, 256>>>(h0, z0);                                                 // 1
    splitA_k<<<32768, 256>>>(A, pAhi, pAlo);                                        // 2
    gemmP_hmma<<<dim3(16, 8, 8), 256, GP3>>>(pAhi, pAlo, pAhi, pAlo,                // 3 (profiled)
        pAhi, pAlo, NNi, sAA, 0, pA2hi, pA2lo, pA2hi, pA2lo, NNi, sAA, 0);
    gemmP_hmma<<<dim3(16, 5, 16), 256, GP3>>>(pAhi, pAlo, pA2hi, pA2lo,
        pXhi, pXlo, 0, 0, 1, pAX1hi, pAX1lo, pAX2hi, pAX2lo, 0, 0, 1);
    gemmP_hmma<<<dim3(16, 1, 16), 256, GP3>>>(pAhi, pAlo, pA2hi, pA2lo,
        pShi, pSlo, 128, sS, 0, pB1hi, pB1lo, pB2hi, pB2lo, 128, sS, 0);
    splitW_k<<<48, 256>>>(oV_W0,   pOW0hi,           pOW0lo,           192, 64, 64);
    splitW_k<<<48, 256>>>(oG_W0,   pOW0hi + 12288,   pOW0lo + 12288,   192, 64, 64);
    splitW_k<<<16, 256>>>(oV_Wout, pOWouthi,         pOWoutlo,         64, 64, 64);
    splitW_k<<<16, 256>>>(oG_Wout, pOWouthi + 4096,  pOWoutlo + 4096,  64, 64, 64);
    splitW_k<<<128, 256>>>(gV_Wg,  pGWghi,           pGWglo,           240, 128, 128);
    splitW_k<<<128, 256>>>(gG_Wg,  pGWghi + 32768,   pGWglo + 32768,   240, 128, 128);
    splitW_k<<<64, 256>>>(gV_Wc,   pGWchi,           pGWclo,           240, 64, 64);
    splitW_k<<<64, 256>>>(gG_Wc,   pGWchi + 16384,   pGWclo + 16384,   240, 64, 64);
    splitW_k<<<16, 256>>>(Wz1, pHWhi,         pHWlo,         64, 64, 64);
    splitW_k<<<16, 256>>>(Wz2, pHWhi + 4096,  pHWlo + 4096,  64, 64, 64);
    splitW_k<<<16, 256>>>(Wz3, pHWhi + 8192,  pHWlo + 8192,  64, 64, 64);
    splitW_k<<<16, 256>>>(Wo,  pHWhi + 12288, pHWlo + 12288, 64, 16, 64);

    dim3 mmaG(16, 1, 16);
    for (int t = 0; t < TTi; t++) {
        for (int sub = 0; sub < 2; sub++) {
            if (t || sub)
                gemmP_hmma<<<mmaG, 256, GP3>>>(pAhi, pAlo, pA2hi, pA2lo,
                    pShi, pSlo, 128, sS, 0, pB1hi, pB1lo, pB2hi, pB2lo, 128, sS, 0);
            denseODE_k<<<dim3(128, 1, 2), 256, OD_SMEM>>>((sub == 1) ? t : -1,
                pOW0hi, pOW0lo, pOWouthi, pOWoutlo, oV_b0, oG_b0, oV_bout, oG_bout);
        }
        if (t < TTi - 1) {
            gemmP_hmma<<<mmaG, 256, GP3>>>(pAhi, pAlo, pA2hi, pA2lo,
                pShi, pSlo, 128, sS, 0, pB1hi, pB1lo, pB2hi, pB2lo, 128, sS, 0);
            denseG_k<<<dim3(128, 1, 2), 256, DG_SMEM>>>(t,
                pShi, pSlo, pGWghi, pGWglo, pGWghi + 32768, pGWglo + 32768,
                gV_bg, gG_bg);
            gemmP_hmma<<<mmaG, 256, GP3>>>(pAhi, pAlo, pA2hi, pA2lo,
                pRHhi, pRHlo, 128, sS, 0, pB1hi, pB1lo, pB2hi, pB2lo, 128, sS, 0);
            denseH_k<<<dim3(64, 1, 2), 256, DH_SMEM>>>(240, 8, 3, t,
                pRHhi, pRHlo, pGWchi, pGWclo, pGWchi + 16384, pGWclo + 16384, 64,
                gV_bc, gG_bc);
        }
    }

    // fused output head over t = 1..39 (rows 319488 = 4992 * 64)
    headF_k<<<4992, 256, HF_SMEM>>>(bz1, bz2, bz3, bo, (float*)d_out);
}

// round 16
// speedup vs baseline: 1.1214x; 1.0148x over previous
#include <cuda_runtime.h>
#include <cuda_bf16.h>
#include <cstdint>

#define NNi   1024
#define BBi   8
#define TTi   40
#define DINi  16
#define ROWSi 8192
#define DT_SUB 0.025f

typedef __nv_bfloat16 bf16;

// ------------------- static scratch (no runtime allocation) -------------------
__device__ float g_obs[(size_t)BBi*TTi*NNi];
__device__ float g_S  [(size_t)ROWSi*128];
__device__ float g_u  [(size_t)ROWSi*128];
__device__ float g_pre[(size_t)TTi*ROWSi*128];
// bf16 split operand twins
__device__ bf16 g_Ahi  [(size_t)BBi*NNi*NNi];
__device__ bf16 g_Alo  [(size_t)BBi*NNi*NNi];
__device__ bf16 g_A2hi [(size_t)BBi*NNi*NNi];
__device__ bf16 g_A2lo [(size_t)BBi*NNi*NNi];
__device__ bf16 g_Shi  [(size_t)ROWSi*128];
__device__ bf16 g_Slo  [(size_t)ROWSi*128];
__device__ bf16 g_RHhi [(size_t)ROWSi*128];
__device__ bf16 g_RHlo [(size_t)ROWSi*128];
__device__ bf16 g_B1hi [(size_t)ROWSi*128];
__device__ bf16 g_B1lo [(size_t)ROWSi*128];
__device__ bf16 g_B2hi [(size_t)ROWSi*128];
__device__ bf16 g_B2lo [(size_t)ROWSi*128];
__device__ bf16 g_Xhi  [(size_t)BBi*TTi*NNi*DINi];
__device__ bf16 g_Xlo  [(size_t)BBi*TTi*NNi*DINi];
__device__ bf16 g_AX1hi[(size_t)BBi*TTi*NNi*DINi];
__device__ bf16 g_AX1lo[(size_t)BBi*TTi*NNi*DINi];
__device__ bf16 g_AX2hi[(size_t)BBi*TTi*NNi*DINi];
__device__ bf16 g_AX2lo[(size_t)BBi*TTi*NNi*DINi];
__device__ bf16 g_preZhi[(size_t)39*ROWSi*64];
__device__ bf16 g_preZlo[(size_t)39*ROWSi*64];
__device__ bf16 g_zero_bf[16];
// padded bf16 weight splits
__device__ bf16 g_oW0hi  [2*192*64];
__device__ bf16 g_oW0lo  [2*192*64];
__device__ bf16 g_oWouthi[2*64*64];
__device__ bf16 g_oWoutlo[2*64*64];
__device__ bf16 g_gWghi  [2*256*128];
__device__ bf16 g_gWglo  [2*256*128];
__device__ bf16 g_gWchi  [2*256*64];
__device__ bf16 g_gWclo  [2*256*64];
__device__ bf16 g_hWhi   [4*64*64];     // Wz1,Wz2,Wz3,Wo(pad)
__device__ bf16 g_hWlo   [4*64*64];

// ------------------- asm helpers -------------------
__device__ __forceinline__ uint32_t smem_u32(const void* p) {
    uint32_t a;
    asm("{ .reg .u64 t; cvta.to.shared.u64 t, %1; cvt.u32.u64 %0, t; }" : "=r"(a) : "l"(p));
    return a;
}
__device__ __forceinline__ void ldm4(uint32_t* r, uint32_t a) {
    asm volatile("ldmatrix.sync.aligned.m8n8.x4.shared.b16 {%0,%1,%2,%3}, [%4];"
        : "=r"(r[0]), "=r"(r[1]), "=r"(r[2]), "=r"(r[3]) : "r"(a));
}
__device__ __forceinline__ void ldm4t(uint32_t* r, uint32_t a) {
    asm volatile("ldmatrix.sync.aligned.m8n8.x4.trans.shared.b16 {%0,%1,%2,%3}, [%4];"
        : "=r"(r[0]), "=r"(r[1]), "=r"(r[2]), "=r"(r[3]) : "r"(a));
}
__device__ __forceinline__ void mma_bf(float* c, const uint32_t* a, uint32_t b0, uint32_t b1) {
    asm volatile("mma.sync.aligned.m16n8k16.row.col.f32.bf16.bf16.f32 "
        "{%0,%1,%2,%3}, {%4,%5,%6,%7}, {%8,%9}, {%0,%1,%2,%3};"
        : "+f"(c[0]), "+f"(c[1]), "+f"(c[2]), "+f"(c[3])
        : "r"(a[0]), "r"(a[1]), "r"(a[2]), "r"(a[3]), "r"(b0), "r"(b1));
}
__device__ __forceinline__ void cpa16(uint32_t sm, const void* gm) {
    asm volatile("cp.async.cg.shared.global [%0], [%1], 16;"
        :: "r"(sm), "l"(__cvta_generic_to_global(gm)));
}
#define CP_COMMIT() asm volatile("cp.async.commit_group;" ::: "memory")
#define CP_WAIT0()  asm volatile("cp.async.wait_group 0;" ::: "memory")
#define CP_WAIT1()  asm volatile("cp.async.wait_group 1;" ::: "memory")

__device__ __forceinline__ void split_bf(float v, bf16& h, bf16& l) {
    h = __float2bfloat16_rn(v);
    l = __float2bfloat16_rn(v - __bfloat162float(h));
}

// ------------------- init / split kernels -------------------
__global__ void initX_k(const float4* __restrict__ v, const float4* __restrict__ m) {
    int i = blockIdx.x * 256 + threadIdx.x;
    float s = 0.f;
#pragma unroll
    for (int q = 0; q < 4; q++) {
        float4 vv = v[i * 4 + q], mm = m[i * 4 + q];
        s += fabsf(mm.x) + fabsf(mm.y) + fabsf(mm.z) + fabsf(mm.w);
        float4 x = make_float4(vv.x * mm.x, vv.y * mm.y, vv.z * mm.z, vv.w * mm.w);
        size_t o = (size_t)i * 16 + q * 4;
        split_bf(x.x, g_Xhi[o + 0], g_Xlo[o + 0]);
        split_bf(x.y, g_Xhi[o + 1], g_Xlo[o + 1]);
        split_bf(x.z, g_Xhi[o + 2], g_Xlo[o + 2]);
        split_bf(x.w, g_Xhi[o + 3], g_Xlo[o + 3]);
    }
    g_obs[i] = (s > 1e-4f) ? 1.f : 0.f;
}
__global__ void initS_k(const float* __restrict__ h0, const float* __restrict__ z0) {
    int i = blockIdx.x * 256 + threadIdx.x;
    int c = i & 127;
    float v = (c < 64) ? h0[c] : z0[c - 64];
    g_S[i] = v;
    split_bf(v, g_Shi[i], g_Slo[i]);
}
__global__ void splitA_k(const float* __restrict__ src, bf16* __restrict__ hi, bf16* __restrict__ lo) {
    size_t i = (size_t)blockIdx.x * 256 + threadIdx.x;
    split_bf(src[i], hi[i], lo[i]);
}
__global__ void splitW_k(const float* __restrict__ src, bf16* __restrict__ hi, bf16* __restrict__ lo,
                         int K, int N, int Npad) {
    int i = blockIdx.x * 256 + threadIdx.x;
    int k = i / Npad, n = i - k * Npad;
    float v = (k < K && n < N) ? src[k * N + n] : 0.f;
    split_bf(v, hi[i], lo[i]);
}

// ------------------- feature gather decode (GRU K=240 layout) -------------------
__device__ __forceinline__ const bf16* gru_feat(
    int kk, int Kdim, int grow, int z, int t, int arr,
    const bf16* __restrict__ Hhi, const bf16* __restrict__ Hlo)
{
    if (kk >= Kdim) return g_zero_bf;
    int bb = grow >> 10, n = grow & 1023;
    size_t xb = (((size_t)bb * TTi + t) * NNi + n) * 16;
    const bf16 *hi, *lo; size_t o2;
    if (kk < 16)       { hi = g_Xhi;   lo = g_Xlo;   o2 = xb + kk; }
    else if (kk < 80)  { hi = Hhi;     lo = Hlo;     o2 = (size_t)grow * 128 + z * 64 + (kk - 16); }
    else if (kk < 96)  { hi = g_AX1hi; lo = g_AX1lo; o2 = xb + (kk - 80); }
    else if (kk < 160) { hi = g_B1hi;  lo = g_B1lo;  o2 = (size_t)grow * 128 + z * 64 + (kk - 96); }
    else if (kk < 176) { hi = g_AX2hi; lo = g_AX2lo; o2 = xb + (kk - 160); }
    else               { hi = g_B2hi;  lo = g_B2lo;  o2 = (size_t)grow * 128 + z * 64 + (kk - 176); }
    return (arr ? lo : hi) + o2;
}

// ------------------- diffusion GEMM (64x128 tile, K=1024, 3-stage) -------------------
#define GP_STAGE  27648
#define A_LO_OFF  5120
#define B_OFF     10240
#define B_LO_OFF  8704

__device__ __forceinline__ void gp_load(
    uint32_t so, int k0, int row0, int col0, int bT,
    const bf16* __restrict__ Ah, const bf16* __restrict__ Al,
    const bf16* __restrict__ Bh, const bf16* __restrict__ Bl,
    int ldb, int bxmode)
{
    int t = threadIdx.x;
#pragma unroll
    for (int i = 0; i < 2; i++) {
        int c = t + i * 256;
        int arr = c >> 8, cc = c & 255, row = cc >> 2, seg = cc & 3;
        const bf16* g = (arr ? Al : Ah) + (size_t)(row0 + row) * NNi + k0 + seg * 8;
        cpa16(so + arr * A_LO_OFF + row * 80 + seg * 16, g);
    }
#pragma unroll
    for (int i = 0; i < 4; i++) {
        int c = t + i * 256;
        int arr = c >> 9, cc = c & 511, k = cc >> 4, seg = cc & 15;
        size_t off;
        if (bxmode) {
            int col = col0 + seg * 8;
            off = ((size_t)(bT + (col >> 4)) * NNi + (k0 + k)) * 16 + (col & 15);
        } else {
            off = (size_t)(k0 + k) * ldb + col0 + seg * 8;
        }
        cpa16(so + B_OFF + arr * B_LO_OFF + k * 272 + seg * 16, (arr ? Bl : Bh) + off);
    }
    CP_COMMIT();
}

__global__ void __launch_bounds__(256, 2) gemmP_hmma(
    const bf16* __restrict__ Ahi1, const bf16* __restrict__ Alo1,
    const bf16* __restrict__ Ahi2, const bf16* __restrict__ Alo2,
    const bf16* __restrict__ Bhi, const bf16* __restrict__ Blo,
    int ldb, size_t bstride, int bxmode,
    bf16* __restrict__ O1hi, bf16* __restrict__ O1lo,
    bf16* __restrict__ O2hi, bf16* __restrict__ O2lo,
    int ldo, size_t ostride, int oxmode)
{
    extern __shared__ char smraw[];
    int bz = blockIdx.z;
    int b = bz & 7, hop = bz >> 3;
    const bf16* Ah = (hop ? Ahi2 : Ahi1) + (size_t)b * NNi * NNi;
    const bf16* Al = (hop ? Alo2 : Alo1) + (size_t)b * NNi * NNi;
    const bf16* Bh = bxmode ? Bhi : Bhi + (size_t)b * bstride;
    const bf16* Bl = bxmode ? Blo : Blo + (size_t)b * bstride;
    bf16* Ohi = (hop ? O2hi : O1hi) + (oxmode ? 0 : (size_t)b * ostride);
    bf16* Olo = (hop ? O2lo : O1lo) + (oxmode ? 0 : (size_t)b * ostride);
    int row0 = blockIdx.x * 64, col0 = blockIdx.y * 128;
    int bT = b * TTi;

    int t = threadIdx.x, wid = t >> 5, lane = t & 31;
    int wm = (wid & 1) * 32, wn = (wid >> 1) * 32;
    uint32_t sbase = smem_u32(smraw);

    float acc[2][4][4];
#pragma unroll
    for (int mt = 0; mt < 2; mt++)
#pragma unroll
        for (int nt = 0; nt < 4; nt++)
#pragma unroll
            for (int q = 0; q < 4; q++) acc[mt][nt][q] = 0.f;

    uint32_t lmRow  = lane & 15;
    uint32_t lmColB = (lane >> 4) * 16;

    gp_load(sbase,            0,  row0, col0, bT, Ah, Al, Bh, Bl, ldb, bxmode);
    gp_load(sbase + GP_STAGE, 32, row0, col0, bT, Ah, Al, Bh, Bl, ldb, bxmode);

    int s0 = 0, s1 = 1, s2 = 2;
    for (int kt = 0; kt < 32; kt++) {
        if (kt < 31) { CP_WAIT1(); } else { CP_WAIT0(); }
        __syncthreads();
        if (kt + 2 < 32)
            gp_load(sbase + (uint32_t)s2 * GP_STAGE, (kt + 2) * 32, row0, col0, bT,
                    Ah, Al, Bh, Bl, ldb, bxmode);

        uint32_t so = sbase + (uint32_t)s0 * GP_STAGE;
#pragma unroll
        for (int ks = 0; ks < 2; ks++) {
            uint32_t ah[2][4], al[2][4];
#pragma unroll
            for (int mt = 0; mt < 2; mt++) {
                uint32_t ad = so + (wm + mt * 16 + lmRow) * 80 + ks * 32 + lmColB;
                ldm4(ah[mt], ad);
                ldm4(al[mt], ad + A_LO_OFF);
            }
#pragma unroll
            for (int np = 0; np < 2; np++) {
                uint32_t bd = so + B_OFF + (ks * 16 + lmRow) * 272 + (wn + np * 16) * 2 + lmColB;
                uint32_t bh[4], bl[4];
                ldm4t(bh, bd);
                ldm4t(bl, bd + B_LO_OFF);
#pragma unroll
                for (int mt = 0; mt < 2; mt++) {
                    mma_bf(acc[mt][2 * np],     ah[mt], bh[0], bh[1]);
                    mma_bf(acc[mt][2 * np + 1], ah[mt], bh[2], bh[3]);
                    mma_bf(acc[mt][2 * np],     ah[mt], bl[0], bl[1]);
                    mma_bf(acc[mt][2 * np + 1], ah[mt], bl[2], bl[3]);
                    mma_bf(acc[mt][2 * np],     al[mt], bh[0], bh[1]);
                    mma_bf(acc[mt][2 * np + 1], al[mt], bh[2], bh[3]);
                }
            }
        }
        int sx = s0; s0 = s1; s1 = s2; s2 = sx;
    }

    int gr = lane >> 2, gc = (lane & 3) * 2;
#pragma unroll
    for (int mt = 0; mt < 2; mt++)
#pragma unroll
        for (int nt = 0; nt < 4; nt++) {
            int r = row0 + wm + mt * 16 + gr;
            int c = col0 + wn + nt * 8 + gc;
#pragma unroll
            for (int half = 0; half < 2; half++) {
                int rr = r + half * 8;
                bf16 h0, l0, h1, l1;
                split_bf(acc[mt][nt][half * 2 + 0], h0, l0);
                split_bf(acc[mt][nt][half * 2 + 1], h1, l1);
                size_t off;
                if (oxmode) off = ((size_t)(bT + (c >> 4)) * NNi + rr) * 16 + (c & 15);
                else        off = (size_t)rr * ldo + c;
                *(__nv_bfloat162*)&Ohi[off] = __halves2bfloat162(h0, h1);
                *(__nv_bfloat162*)&Olo[off] = __halves2bfloat162(l0, l1);
            }
        }
}

// ------------------- epilogue helpers -------------------
__device__ __forceinline__ void dh_epi(int mode, int z, int t, int row, int col, float v) {
    if (mode == 2) {
        float g = 1.f / (1.f + expf(-v));
        if (col < 64) {
            size_t ii = (size_t)row * 128 + z * 64 + col;
            float rh = g * g_S[ii];
            split_bf(rh, g_RHhi[ii], g_RHlo[ii]);
        } else {
            g_u[(size_t)row * 128 + z * 64 + (col - 64)] = g;
        }
    } else { // 3
        float cc = tanhf(v);
        size_t ii = (size_t)row * 128 + z * 64 + col;
        float u = g_u[ii], h = g_S[ii];
        float m = g_obs[((size_t)(row >> 10) * TTi + t) * NNi + (row & 1023)];
        float hn = u * h + (1.f - u) * cc;
        float s = h + m * (hn - h);
        g_S[ii] = s;
        split_bf(s, g_Shi[ii], g_Slo[ii]);
    }
}

// ------------------- GRU gate dense: 64x128 tile (gemm-shaped) -------------------
__device__ __forceinline__ void dg_load(
    uint32_t so, int k0, int row0, int z, int t,
    const bf16* __restrict__ Hhi, const bf16* __restrict__ Hlo,
    const bf16* __restrict__ Whi, const bf16* __restrict__ Wlo)
{
    int tid = threadIdx.x;
#pragma unroll
    for (int i = 0; i < 2; i++) {          // A: 64 rows x 32 k, hi+lo
        int c = tid + i * 256;
        int arr = c >> 8, cc = c & 255, row = cc >> 2, seg = cc & 3;
        int kk = k0 + seg * 8;
        cpa16(so + arr * A_LO_OFF + row * 80 + seg * 16,
              gru_feat(kk, 240, row0 + row, z, t, arr, Hhi, Hlo));
    }
#pragma unroll
    for (int i = 0; i < 4; i++) {          // B(Wg): 32 k x 128 cols, hi+lo
        int c = tid + i * 256;
        int arr = c >> 9, cc = c & 511, k = cc >> 4, seg = cc & 15;
        const bf16* w = (arr ? Wlo : Whi) + (size_t)(k0 + k) * 128 + seg * 8;
        cpa16(so + B_OFF + arr * B_LO_OFF + k * 272 + seg * 16, w);
    }
    CP_COMMIT();
}

__global__ void __launch_bounds__(256, 2) denseG_k(
    int t,
    const bf16* __restrict__ Hhi, const bf16* __restrict__ Hlo,
    const bf16* __restrict__ W0hi, const bf16* __restrict__ W0lo,
    const bf16* __restrict__ W1hi, const bf16* __restrict__ W1lo,
    const float* __restrict__ bias0, const float* __restrict__ bias1)
{
    extern __shared__ char smraw[];
    int z = blockIdx.z;
    int row0 = blockIdx.x * 64;
    const bf16* Whi = z ? W1hi : W0hi;
    const bf16* Wlo = z ? W1lo : W0lo;
    const float* bias = z ? bias1 : bias0;

    int tid = threadIdx.x, wid = tid >> 5, lane = tid & 31;
    int wm = (wid & 1) * 32, wn = (wid >> 1) * 32;
    uint32_t sbase = smem_u32(smraw);
    uint32_t lmRow = lane & 15, lmColB = (lane >> 4) * 16;

    float acc[2][4][4];
#pragma unroll
    for (int mt = 0; mt < 2; mt++)
#pragma unroll
        for (int nt = 0; nt < 4; nt++)
#pragma unroll
            for (int q = 0; q < 4; q++) acc[mt][nt][q] = 0.f;

    dg_load(sbase,            0,  row0, z, t, Hhi, Hlo, Whi, Wlo);
    dg_load(sbase + GP_STAGE, 32, row0, z, t, Hhi, Hlo, Whi, Wlo);

    for (int kt = 0; kt < 8; kt++) {
        if (kt < 7) { CP_WAIT1(); } else { CP_WAIT0(); }
        __syncthreads();

        uint32_t so = sbase + (uint32_t)(kt & 1) * GP_STAGE;
#pragma unroll
        for (int ks = 0; ks < 2; ks++) {
            uint32_t ah[2][4], al[2][4];
#pragma unroll
            for (int mt = 0; mt < 2; mt++) {
                uint32_t ad = so + (wm + mt * 16 + lmRow) * 80 + ks * 32 + lmColB;
                ldm4(ah[mt], ad);
                ldm4(al[mt], ad + A_LO_OFF);
            }
#pragma unroll
            for (int np = 0; np < 2; np++) {
                uint32_t bd = so + B_OFF + (ks * 16 + lmRow) * 272 + (wn + np * 16) * 2 + lmColB;
                uint32_t bh[4], bl[4];
                ldm4t(bh, bd);
                ldm4t(bl, bd + B_LO_OFF);
#pragma unroll
                for (int mt = 0; mt < 2; mt++) {
                    mma_bf(acc[mt][2 * np],     ah[mt], bh[0], bh[1]);
                    mma_bf(acc[mt][2 * np + 1], ah[mt], bh[2], bh[3]);
                    mma_bf(acc[mt][2 * np],     ah[mt], bl[0], bl[1]);
                    mma_bf(acc[mt][2 * np + 1], ah[mt], bl[2], bl[3]);
                    mma_bf(acc[mt][2 * np],     al[mt], bh[0], bh[1]);
                    mma_bf(acc[mt][2 * np + 1], al[mt], bh[2], bh[3]);
                }
            }
        }
        __syncthreads();
        if (kt + 2 < 8)
            dg_load(sbase + (uint32_t)(kt & 1) * GP_STAGE, (kt + 2) * 32, row0, z, t,
                    Hhi, Hlo, Whi, Wlo);
    }

    int gr = lane >> 2, gc = (lane & 3) * 2;
#pragma unroll
    for (int mt = 0; mt < 2; mt++)
#pragma unroll
        for (int nt = 0; nt < 4; nt++) {
            int r = row0 + wm + mt * 16 + gr;
            int c = wn + nt * 8 + gc;
            dh_epi(2, z, t, r,     c,     acc[mt][nt][0] + bias[c]);
            dh_epi(2, z, t, r,     c + 1, acc[mt][nt][1] + bias[c + 1]);
            dh_epi(2, z, t, r + 8, c,     acc[mt][nt][2] + bias[c]);
            dh_epi(2, z, t, r + 8, c + 1, acc[mt][nt][3] + bias[c + 1]);
        }
}

// ------------------- GRU cand dense: 64x64 tile (ODE-shaped stage) -------------------
#define OD_ALO   5120
#define OD_B     10240
#define OD_BLO   4608
#define OD_STAGE 19456
#define OD_H1HI  38912
#define OD_H1LO  48128
#define OD_SMEM  57344

__device__ __forceinline__ void dc_load(
    uint32_t so, int k0, int row0, int z, int t,
    const bf16* __restrict__ Hhi, const bf16* __restrict__ Hlo,
    const bf16* __restrict__ Whi, const bf16* __restrict__ Wlo)
{
    int tid = threadIdx.x;
#pragma unroll
    for (int i = 0; i < 2; i++) {          // A: 64 rows x 32 k, hi+lo
        int c = tid + i * 256;
        int arr = c >> 8, cc = c & 255, row = cc >> 2, seg = cc & 3;
        int kk = k0 + seg * 8;
        cpa16(so + arr * OD_ALO + row * 80 + seg * 16,
              gru_feat(kk, 240, row0 + row, z, t, arr, Hhi, Hlo));
    }
#pragma unroll
    for (int i = 0; i < 2; i++) {          // B(Wc): 32 k x 64 cols, hi+lo
        int c = tid + i * 256;
        int arr = c >> 8, cc = c & 255, k = cc >> 3, seg = cc & 7;
        const bf16* w = (arr ? Wlo : Whi) + (size_t)(k0 + k) * 64 + seg * 8;
        cpa16(so + OD_B + arr * OD_BLO + k * 144 + seg * 16, w);
    }
    CP_COMMIT();
}

__global__ void __launch_bounds__(256, 2) denseC_k(
    int t,
    const bf16* __restrict__ Hhi, const bf16* __restrict__ Hlo,
    const bf16* __restrict__ W0hi, const bf16* __restrict__ W0lo,
    const bf16* __restrict__ W1hi, const bf16* __restrict__ W1lo,
    const float* __restrict__ bias0, const float* __restrict__ bias1)
{
    extern __shared__ char smraw[];
    int z = blockIdx.z;
    int row0 = blockIdx.x * 64;
    const bf16* Whi = z ? W1hi : W0hi;
    const bf16* Wlo = z ? W1lo : W0lo;
    const float* bias = z ? bias1 : bias0;

    int tid = threadIdx.x, wid = tid >> 5, lane = tid & 31;
    int wm = (wid & 3) * 16, wn = (wid >> 2) * 32;   // 4x2 warps on 64x64
    uint32_t sb = smem_u32(smraw);
    uint32_t lmRow = lane & 15, lmColB = (lane >> 4) * 16;
    int gr = lane >> 2, gc = (lane & 3) * 2;

    float acc[4][4];
#pragma unroll
    for (int nt = 0; nt < 4; nt++)
#pragma unroll
        for (int q = 0; q < 4; q++) acc[nt][q] = 0.f;

    dc_load(sb, 0, row0, z, t, Hhi, Hlo, Whi, Wlo);
    for (int kt = 0; kt < 8; kt++) {
        if (kt < 7)
            dc_load(sb + ((kt + 1) & 1) * OD_STAGE, (kt + 1) * 32, row0, z, t, Hhi, Hlo, Whi, Wlo);
        if (kt < 7) { CP_WAIT1(); } else { CP_WAIT0(); }
        __syncthreads();
        uint32_t so = sb + (kt & 1) * OD_STAGE;
#pragma unroll
        for (int ks = 0; ks < 2; ks++) {
            uint32_t ah[4], al[4];
            uint32_t ad = so + (wm + lmRow) * 80 + ks * 32 + lmColB;
            ldm4(ah, ad);
            ldm4(al, ad + OD_ALO);
#pragma unroll
            for (int np = 0; np < 2; np++) {
                uint32_t bd = so + OD_B + (ks * 16 + lmRow) * 144 + (wn + np * 16) * 2 + lmColB;
                uint32_t bh[4], bl[4];
                ldm4t(bh, bd);
                ldm4t(bl, bd + OD_BLO);
                mma_bf(acc[2 * np],     ah, bh[0], bh[1]);
                mma_bf(acc[2 * np + 1], ah, bh[2], bh[3]);
                mma_bf(acc[2 * np],     ah, bl[0], bl[1]);
                mma_bf(acc[2 * np + 1], ah, bl[2], bl[3]);
                mma_bf(acc[2 * np],     al, bh[0], bh[1]);
                mma_bf(acc[2 * np + 1], al, bh[2], bh[3]);
            }
        }
        __syncthreads();
    }

#pragma unroll
    for (int nt = 0; nt < 4; nt++) {
        int r = row0 + wm + gr;
        int c = wn + nt * 8 + gc;
        dh_epi(3, z, t, r,     c,     acc[nt][0] + bias[c]);
        dh_epi(3, z, t, r,     c + 1, acc[nt][1] + bias[c + 1]);
        dh_epi(3, z, t, r + 8, c,     acc[nt][2] + bias[c]);
        dh_epi(3, z, t, r + 8, c + 1, acc[nt][3] + bias[c + 1]);
    }
}

// ------------------- fused ODE step, 64-row tiles -------------------
__device__ __forceinline__ void ode_load64(
    uint32_t so, int k0, int row0, int z,
    const bf16* __restrict__ Whi, const bf16* __restrict__ Wlo)
{
#pragma unroll
    for (int i = 0; i < 2; i++) {
        int c = threadIdx.x + i * 256;
        int arr = c >> 8, cc = c & 255;
        int row = cc >> 2, seg = cc & 3;
        int kk = k0 + seg * 8;
        int grow = row0 + row;
        const bf16 *hi, *lo; int kloc;
        if (kk < 64)       { hi = g_Shi;  lo = g_Slo;  kloc = kk; }
        else if (kk < 128) { hi = g_B1hi; lo = g_B1lo; kloc = kk - 64; }
        else               { hi = g_B2hi; lo = g_B2lo; kloc = kk - 128; }
        const bf16* src = arr ? lo : hi;
        size_t off = (size_t)grow * 128 + z * 64 + kloc;
        cpa16(so + arr * OD_ALO + row * 80 + seg * 16, src + off);
    }
#pragma unroll
    for (int i = 0; i < 2; i++) {
        int c = threadIdx.x + i * 256;
        int arr = c >> 8, cc = c & 255;
        int k = cc >> 3, seg = cc & 7;
        const bf16* w = (arr ? Wlo : Whi) + (size_t)(k0 + k) * 64 + seg * 8;
        cpa16(so + OD_B + arr * OD_BLO + k * 144 + seg * 16, w);
    }
    CP_COMMIT();
}

__global__ void __launch_bounds__(256, 2) denseODE_k(
    int t_pre,
    const bf16* __restrict__ W0hi, const bf16* __restrict__ W0lo,
    const bf16* __restrict__ Wouthi, const bf16* __restrict__ Woutlo,
    const float* __restrict__ b0_0, const float* __restrict__ b0_1,
    const float* __restrict__ bo_0, const float* __restrict__ bo_1)
{
    extern __shared__ char smraw[];
    int z = blockIdx.z;
    int row0 = blockIdx.x * 64;
    const bf16* Whi = W0hi + (size_t)z * 12288;
    const bf16* Wlo = W0lo + (size_t)z * 12288;
    const bf16* WoH = Wouthi + (size_t)z * 4096;
    const bf16* WoL = Woutlo + (size_t)z * 4096;
    const float* b0 = z ? b0_1 : b0_0;
    const float* bo = z ? bo_1 : bo_0;

    int tid = threadIdx.x, wid = tid >> 5, lane = tid & 31;
    int wm = (wid & 3) * 16, wn = (wid >> 2) * 32;
    uint32_t sb = smem_u32(smraw);
    uint32_t lmRow = lane & 15, lmColB = (lane >> 4) * 16;
    int gr = lane >> 2, gc = (lane & 3) * 2;

    float acc[4][4];
#pragma unroll
    for (int nt = 0; nt < 4; nt++)
#pragma unroll
        for (int q = 0; q < 4; q++) acc[nt][q] = 0.f;

    ode_load64(sb, 0, row0, z, Whi, Wlo);
    for (int kt = 0; kt < 6; kt++) {
        if (kt < 5)
            ode_load64(sb + ((kt + 1) & 1) * OD_STAGE, (kt + 1) * 32, row0, z, Whi, Wlo);
        if (kt < 5) { CP_WAIT1(); } else { CP_WAIT0(); }
        __syncthreads();
        uint32_t so = sb + (kt & 1) * OD_STAGE;
#pragma unroll
        for (int ks = 0; ks < 2; ks++) {
            uint32_t ah[4], al[4];
            uint32_t ad = so + (wm + lmRow) * 80 + ks * 32 + lmColB;
            ldm4(ah, ad);
            ldm4(al, ad + OD_ALO);
#pragma unroll
            for (int np = 0; np < 2; np++) {
                uint32_t bd = so + OD_B + (ks * 16 + lmRow) * 144 + (wn + np * 16) * 2 + lmColB;
                uint32_t bh[4], bl[4];
                ldm4t(bh, bd);
                ldm4t(bl, bd + OD_BLO);
                mma_bf(acc[2 * np],     ah, bh[0], bh[1]);
                mma_bf(acc[2 * np + 1], ah, bh[2], bh[3]);
                mma_bf(acc[2 * np],     ah, bl[0], bl[1]);
                mma_bf(acc[2 * np + 1], ah, bl[2], bl[3]);
                mma_bf(acc[2 * np],     al, bh[0], bh[1]);
                mma_bf(acc[2 * np + 1], al, bh[2], bh[3]);
            }
        }
        __syncthreads();
    }

#pragma unroll
    for (int nt = 0; nt < 4; nt++) {
        int rl = wm + gr;
        int c = wn + nt * 8 + gc;
        float v0 = tanhf(acc[nt][0] + b0[c]);
        float v1 = tanhf(acc[nt][1] + b0[c + 1]);
        float v2 = tanhf(acc[nt][2] + b0[c]);
        float v3 = tanhf(acc[nt][3] + b0[c + 1]);
        bf16 h0, l0, h1, l1;
        split_bf(v0, h0, l0); split_bf(v1, h1, l1);
        *(__nv_bfloat162*)(smraw + OD_H1HI + rl * 144 + c * 2) = __halves2bfloat162(h0, h1);
        *(__nv_bfloat162*)(smraw + OD_H1LO + rl * 144 + c * 2) = __halves2bfloat162(l0, l1);
        split_bf(v2, h0, l0); split_bf(v3, h1, l1);
        *(__nv_bfloat162*)(smraw + OD_H1HI + (rl + 8) * 144 + c * 2) = __halves2bfloat162(h0, h1);
        *(__nv_bfloat162*)(smraw + OD_H1LO + (rl + 8) * 144 + c * 2) = __halves2bfloat162(l0, l1);
    }
    __syncthreads();

#pragma unroll
    for (int i = 0; i < 4; i++) {
        int c = tid + i * 256;
        int arr = c >> 9, cc = c & 511, k = cc >> 3, seg = cc & 7;
        *(uint4*)(smraw + arr * 9216 + k * 144 + seg * 16) =
            *(const uint4*)((arr ? WoL : WoH) + (size_t)k * 64 + seg * 8);
    }
    __syncthreads();

#pragma unroll
    for (int nt = 0; nt < 4; nt++)
#pragma unroll
        for (int q = 0; q < 4; q++) acc[nt][q] = 0.f;

#pragma unroll
    for (int ks = 0; ks < 4; ks++) {
        uint32_t ah[4], al[4];
        uint32_t ad = sb + OD_H1HI + (wm + lmRow) * 144 + ks * 32 + lmColB;
        ldm4(ah, ad);
        ldm4(al, ad + (OD_H1LO - OD_H1HI));
#pragma unroll
        for (int np = 0; np < 2; np++) {
            uint32_t bd = sb + (ks * 16 + lmRow) * 144 + (wn + np * 16) * 2 + lmColB;
            uint32_t bh[4], bl[4];
            ldm4t(bh, bd);
            ldm4t(bl, bd + 9216);
            mma_bf(acc[2 * np],     ah, bh[0], bh[1]);
            mma_bf(acc[2 * np + 1], ah, bh[2], bh[3]);
            mma_bf(acc[2 * np],     ah, bl[0], bl[1]);
            mma_bf(acc[2 * np + 1], ah, bl[2], bl[3]);
            mma_bf(acc[2 * np],     al, bh[0], bh[1]);
            mma_bf(acc[2 * np + 1], al, bh[2], bh[3]);
        }
    }

#pragma unroll
    for (int nt = 0; nt < 4; nt++) {
        int r = row0 + wm + gr;
        int c = wn + nt * 8 + gc;
#pragma unroll
        for (int q = 0; q < 4; q++) {
            int rr = r + (q >> 1) * 8;
            int cc = c + (q & 1);
            size_t ii = (size_t)rr * 128 + z * 64 + cc;
            float s = g_S[ii] + DT_SUB * tanhf(acc[nt][q] + bo[cc]);
            g_S[ii] = s;
            split_bf(s, g_Shi[ii], g_Slo[ii]);
            if (t_pre >= 1) {
                if (z == 0) {
                    g_pre[(size_t)t_pre * ((size_t)ROWSi * 128) + ii] = s;
                } else {
                    size_t pz = ((size_t)(t_pre - 1) * ROWSi + rr) * 64 + cc;
                    split_bf(s, g_preZhi[pz], g_preZlo[pz]);
                }
            }
        }
    }
}

// ------------------- fused output head -------------------
#define HF_A    0
#define HF_ALO  9216
#define HF_W    18432
#define HF_WLO  27648
#define HF_T    36864
#define HF_TLO  46080
#define HF_HVP  55296
#define HF_SMEM 71680

__device__ __forceinline__ void hf_gemm(
    uint32_t sb, uint32_t aOff, uint32_t aLoDelta, float acc[4][4],
    int wm, int wn, uint32_t lmRow, uint32_t lmColB)
{
#pragma unroll
    for (int nt = 0; nt < 4; nt++)
#pragma unroll
        for (int q = 0; q < 4; q++) acc[nt][q] = 0.f;
#pragma unroll
    for (int ks = 0; ks < 4; ks++) {
        uint32_t ah[4], al[4];
        uint32_t ad = sb + aOff + (wm + lmRow) * 144 + ks * 32 + lmColB;
        ldm4(ah, ad);
        ldm4(al, ad + aLoDelta);
#pragma unroll
        for (int np = 0; np < 2; np++) {
            uint32_t bd = sb + HF_W + (ks * 16 + lmRow) * 144 + (wn + np * 16) * 2 + lmColB;
            uint32_t bh[4], bl[4];
            ldm4t(bh, bd);
            ldm4t(bl, bd + 9216);
            mma_bf(acc[2 * np],     ah, bh[0], bh[1]);
            mma_bf(acc[2 * np + 1], ah, bh[2], bh[3]);
            mma_bf(acc[2 * np],     ah, bl[0], bl[1]);
            mma_bf(acc[2 * np + 1], ah, bl[2], bl[3]);
            mma_bf(acc[2 * np],     al, bh[0], bh[1]);
            mma_bf(acc[2 * np + 1], al, bh[2], bh[3]);
        }
    }
}

__device__ __forceinline__ void hf_wcopy(char* smraw, int tid, const bf16* Whi, const bf16* Wlo) {
#pragma unroll
    for (int i = 0; i < 4; i++) {
        int c = tid + i * 256;
        int arr = c >> 9, cc = c & 511, k = cc >> 3, seg = cc & 7;
        *(uint4*)(smraw + HF_W + arr * 9216 + k * 144 + seg * 16) =
            *(const uint4*)((arr ? Wlo : Whi) + (size_t)k * 64 + seg * 8);
    }
}

__global__ void __launch_bounds__(256, 2) headF_k(
    const float* __restrict__ bz1, const float* __restrict__ bz2,
    const float* __restrict__ bz3, const float* __restrict__ boo,
    float* __restrict__ out4)
{
    extern __shared__ char smraw[];
    int row0 = blockIdx.x * 64;
    int tid = threadIdx.x, wid = tid >> 5, lane = tid & 31;
    int wm = (wid & 3) * 16, wn = (wid >> 2) * 32;
    uint32_t sb = smem_u32(smraw);
    uint32_t lmRow = lane & 15, lmColB = (lane >> 4) * 16;
    int gr = lane >> 2, gc = (lane & 3) * 2;

#pragma unroll
    for (int i = 0; i < 4; i++) {
        int c = tid + i * 256;
        int arr = c >> 9, cc = c & 511, row = cc >> 3, seg = cc & 7;
        const bf16* src = (arr ? g_preZlo : g_preZhi) + (size_t)(row0 + row) * 64 + seg * 8;
        cpa16(sb + HF_A + arr * 9216 + row * 144 + seg * 16, src);
    }
#pragma unroll
    for (int i = 0; i < 4; i++) {
        int c = tid + i * 256;
        int arr = c >> 9, cc = c & 511, k = cc >> 3, seg = cc & 7;
        const bf16* w = (arr ? g_hWlo : g_hWhi) + (size_t)k * 64 + seg * 8;
        cpa16(sb + HF_W + arr * 9216 + k * 144 + seg * 16, w);
    }
#pragma unroll
    for (int i = 0; i < 4; i++) {
        int c = tid + i * 256;
        int row = c >> 4, seg = c & 15;
        const float* src = &g_pre[(size_t)(row0 + row + ROWSi) * 128 + seg * 4];
        cpa16(sb + HF_HVP + row * 256 + seg * 16, src);
    }
    CP_COMMIT();
    CP_WAIT0();
    __syncthreads();

    float acc[4][4];
    hf_gemm(sb, HF_A, 9216, acc, wm, wn, lmRow, lmColB);
#pragma unroll
    for (int nt = 0; nt < 4; nt++) {
        int rl = wm + gr;
        int c = wn + nt * 8 + gc;
        float v0 = tanhf(acc[nt][0] + bz1[c]);
        float v1 = tanhf(acc[nt][1] + bz1[c + 1]);
        float v2 = tanhf(acc[nt][2] + bz1[c]);
        float v3 = tanhf(acc[nt][3] + bz1[c + 1]);
        bf16 h0, l0, h1, l1;
        split_bf(v0, h0, l0); split_bf(v1, h1, l1);
        *(__nv_bfloat162*)(smraw + HF_T   + rl * 144 + c * 2) = __halves2bfloat162(h0, h1);
        *(__nv_bfloat162*)(smraw + HF_TLO + rl * 144 + c * 2) = __halves2bfloat162(l0, l1);
        split_bf(v2, h0, l0); split_bf(v3, h1, l1);
        *(__nv_bfloat162*)(smraw + HF_T   + (rl + 8) * 144 + c * 2) = __halves2bfloat162(h0, h1);
        *(__nv_bfloat162*)(smraw + HF_TLO + (rl + 8) * 144 + c * 2) = __halves2bfloat162(l0, l1);
    }
    __syncthreads();

    hf_wcopy(smraw, tid, g_hWhi + 4096, g_hWlo + 4096);
    __syncthreads();
    hf_gemm(sb, HF_T, 9216, acc, wm, wn, lmRow, lmColB);
#pragma unroll
    for (int nt = 0; nt < 4; nt++) {
        int rl = wm + gr;
        int c = wn + nt * 8 + gc;
        float v0 = tanhf(acc[nt][0] + bz2[c]);
        float v1 = tanhf(acc[nt][1] + bz2[c + 1]);
        float v2 = tanhf(acc[nt][2] + bz2[c]);
        float v3 = tanhf(acc[nt][3] + bz2[c + 1]);
        bf16 h0, l0, h1, l1;
        split_bf(v0, h0, l0); split_bf(v1, h1, l1);
        *(__nv_bfloat162*)(smraw + HF_A   + rl * 144 + c * 2) = __halves2bfloat162(h0, h1);
        *(__nv_bfloat162*)(smraw + HF_ALO + rl * 144 + c * 2) = __halves2bfloat162(l0, l1);
        split_bf(v2, h0, l0); split_bf(v3, h1, l1);
        *(__nv_bfloat162*)(smraw + HF_A   + (rl + 8) * 144 + c * 2) = __halves2bfloat162(h0, h1);
        *(__nv_bfloat162*)(smraw + HF_ALO + (rl + 8) * 144 + c * 2) = __halves2bfloat162(l0, l1);
    }
    __syncthreads();

    hf_wcopy(smraw, tid, g_hWhi + 8192, g_hWlo + 8192);
    __syncthreads();
    hf_gemm(sb, HF_A, 9216, acc, wm, wn, lmRow, lmColB);
#pragma unroll
    for (int nt = 0; nt < 4; nt++) {
        int rl = wm + gr;
        int c = wn + nt * 8 + gc;
#pragma unroll
        for (int q = 0; q < 4; q++) {
            int rrl = rl + (q >> 1) * 8;
            int cc = c + (q & 1);
            float g = 1.f / (1.f + expf(-(acc[nt][q] + bz3[cc])));
            float v = g * *(const float*)(smraw + HF_HVP + rrl * 256 + cc * 4);
            bf16 h0, l0;
            split_bf(v, h0, l0);
            *(bf16*)(smraw + HF_T   + rrl * 144 + cc * 2) = h0;
            *(bf16*)(smraw + HF_TLO + rrl * 144 + cc * 2) = l0;
        }
    }
    __syncthreads();

    hf_wcopy(smraw, tid, g_hWhi + 12288, g_hWlo + 12288);
    __syncthreads();
    hf_gemm(sb, HF_T, 9216, acc, wm, wn, lmRow, lmColB);
#pragma unroll
    for (int nt = 0; nt < 4; nt++) {
        int c = wn + nt * 8 + gc;
#pragma unroll
        for (int q = 0; q < 4; q++) {
            int cc = c + (q & 1);
            if (cc >= 16) continue;
            int rr = row0 + wm + gr + (q >> 1) * 8;
            int tp = rr >> 13, bn = rr & 8191;
            int bb = bn >> 10, n = bn & 1023;
            out4[(((size_t)bb * 39 + tp) * NNi + n) * 16 + cc] = acc[nt][q] + boo[cc];
        }
    }
}

// ------------------- host orchestration -------------------
extern "C" void kernel_launch(void* const* d_in, const int* in_sizes, int n_in,
                              void* d_out, int out_size) {
    const float* values  = (const float*)d_in[0];
    const float* masks   = (const float*)d_in[1];
    const float* A       = (const float*)d_in[2];
    const float* h0      = (const float*)d_in[3];
    const float* z0      = (const float*)d_in[4];
    const float* gV_Wg   = (const float*)d_in[5];
    const float* gV_bg   = (const float*)d_in[6];
    const float* gV_Wc   = (const float*)d_in[7];
    const float* gV_bc   = (const float*)d_in[8];
    const float* gG_Wg   = (const float*)d_in[9];
    const float* gG_bg   = (const float*)d_in[10];
    const float* gG_Wc   = (const float*)d_in[11];
    const float* gG_bc   = (const float*)d_in[12];
    const float* oV_W0   = (const float*)d_in[13];
    const float* oV_b0   = (const float*)d_in[14];
    const float* oV_Wout = (const float*)d_in[15];
    const float* oV_bout = (const float*)d_in[16];
    const float* oG_W0   = (const float*)d_in[17];
    const float* oG_b0   = (const float*)d_in[18];
    const float* oG_Wout = (const float*)d_in[19];
    const float* oG_bout = (const float*)d_in[20];
    const float* Wz1     = (const float*)d_in[21];
    const float* bz1     = (const float*)d_in[22];
    const float* Wz2     = (const float*)d_in[23];
    const float* bz2     = (const float*)d_in[24];
    const float* Wz3     = (const float*)d_in[25];
    const float* bz3     = (const float*)d_in[26];
    const float* Wo      = (const float*)d_in[27];
    const float* bo      = (const float*)d_in[28];

    bf16 *pAhi, *pAlo, *pA2hi, *pA2lo, *pShi, *pSlo, *pRHhi, *pRHlo;
    bf16 *pB1hi, *pB1lo, *pB2hi, *pB2lo, *pXhi, *pXlo;
    bf16 *pAX1hi, *pAX1lo, *pAX2hi, *pAX2lo;
    bf16 *pOW0hi, *pOW0lo, *pOWouthi, *pOWoutlo, *pGWghi, *pGWglo, *pGWchi, *pGWclo;
    bf16 *pHWhi, *pHWlo;
    cudaGetSymbolAddress((void**)&pAhi,  g_Ahi);
    cudaGetSymbolAddress((void**)&pAlo,  g_Alo);
    cudaGetSymbolAddress((void**)&pA2hi, g_A2hi);
    cudaGetSymbolAddress((void**)&pA2lo, g_A2lo);
    cudaGetSymbolAddress((void**)&pShi,  g_Shi);
    cudaGetSymbolAddress((void**)&pSlo,  g_Slo);
    cudaGetSymbolAddress((void**)&pRHhi, g_RHhi);
    cudaGetSymbolAddress((void**)&pRHlo, g_RHlo);
    cudaGetSymbolAddress((void**)&pB1hi, g_B1hi);
    cudaGetSymbolAddress((void**)&pB1lo, g_B1lo);
    cudaGetSymbolAddress((void**)&pB2hi, g_B2hi);
    cudaGetSymbolAddress((void**)&pB2lo, g_B2lo);
    cudaGetSymbolAddress((void**)&pXhi,  g_Xhi);
    cudaGetSymbolAddress((void**)&pXlo,  g_Xlo);
    cudaGetSymbolAddress((void**)&pAX1hi, g_AX1hi);
    cudaGetSymbolAddress((void**)&pAX1lo, g_AX1lo);
    cudaGetSymbolAddress((void**)&pAX2hi, g_AX2hi);
    cudaGetSymbolAddress((void**)&pAX2lo, g_AX2lo);
    cudaGetSymbolAddress((void**)&pOW0hi,   g_oW0hi);
    cudaGetSymbolAddress((void**)&pOW0lo,   g_oW0lo);
    cudaGetSymbolAddress((void**)&pOWouthi, g_oWouthi);
    cudaGetSymbolAddress((void**)&pOWoutlo, g_oWoutlo);
    cudaGetSymbolAddress((void**)&pGWghi,   g_gWghi);
    cudaGetSymbolAddress((void**)&pGWglo,   g_gWglo);
    cudaGetSymbolAddress((void**)&pGWchi,   g_gWchi);
    cudaGetSymbolAddress((void**)&pGWclo,   g_gWclo);
    cudaGetSymbolAddress((void**)&pHWhi,    g_hWhi);
    cudaGetSymbolAddress((void**)&pHWlo,    g_hWlo);

    const int GP3 = 3 * GP_STAGE;            // 82944
    const int DG_SMEM = 2 * GP_STAGE;        // 55296
    const int DC_SMEM = 2 * OD_STAGE;        // 38912
    cudaFuncSetAttribute(gemmP_hmma, cudaFuncAttributeMaxDynamicSharedMemorySize, GP3);
    cudaFuncSetAttribute(denseG_k,   cudaFuncAttributeMaxDynamicSharedMemorySize, DG_SMEM);
    cudaFuncSetAttribute(denseC_k,   cudaFuncAttributeMaxDynamicSharedMemorySize, DC_SMEM);
    cudaFuncSetAttribute(denseODE_k, cudaFuncAttributeMaxDynamicSharedMemorySize, OD_SMEM);
    cudaFuncSetAttribute(headF_k,    cudaFuncAttributeMaxDynamicSharedMemorySize, HF_SMEM);

    const size_t sAA = (size_t)NNi * NNi;
    const size_t sS  = (size_t)NNi * 128;

    initX_k<<<1280, 256>>>((const float4*)values, (const float4*)masks);            // 0
    initS_k<<<4096, 256>>>(h0, z0);                                                 // 1
    splitA_k<<<32768, 256>>>(A, pAhi, pAlo);                                        // 2
    gemmP_hmma<<<dim3(16, 8, 8), 256, GP3>>>(pAhi, pAlo, pAhi, pAlo,                // 3 (profiled)
        pAhi, pAlo, NNi, sAA, 0, pA2hi, pA2lo, pA2hi, pA2lo, NNi, sAA, 0);
    gemmP_hmma<<<dim3(16, 5, 16), 256, GP3>>>(pAhi, pAlo, pA2hi, pA2lo,
        pXhi, pXlo, 0, 0, 1, pAX1hi, pAX1lo, pAX2hi, pAX2lo, 0, 0, 1);
    gemmP_hmma<<<dim3(16, 1, 16), 256, GP3>>>(pAhi, pAlo, pA2hi, pA2lo,
        pShi, pSlo, 128, sS, 0, pB1hi, pB1lo, pB2hi, pB2lo, 128, sS, 0);
    splitW_k<<<48, 256>>>(oV_W0,   pOW0hi,           pOW0lo,           192, 64, 64);
    splitW_k<<<48, 256>>>(oG_W0,   pOW0hi + 12288,   pOW0lo + 12288,   192, 64, 64);
    splitW_k<<<16, 256>>>(oV_Wout, pOWouthi,         pOWoutlo,         64, 64, 64);
    splitW_k<<<16, 256>>>(oG_Wout, pOWouthi + 4096,  pOWoutlo + 4096,  64, 64, 64);
    splitW_k<<<128, 256>>>(gV_Wg,  pGWghi,           pGWglo,           240, 128, 128);
    splitW_k<<<128, 256>>>(gG_Wg,  pGWghi + 32768,   pGWglo + 32768,   240, 128, 128);
    splitW_k<<<64, 256>>>(gV_Wc,   pGWchi,           pGWclo,           240, 64, 64);
    splitW_k<<<64, 256>>>(gG_Wc,   pGWchi + 16384,   pGWclo + 16384,   240, 64, 64);
    splitW_k<<<16, 256>>>(Wz1, pHWhi,         pHWlo,         64, 64, 64);
    splitW_k<<<16, 256>>>(Wz2, pHWhi + 4096,  pHWlo + 4096,  64, 64, 64);
    splitW_k<<<16, 256>>>(Wz3, pHWhi + 8192,  pHWlo + 8192,  64, 64, 64);
    splitW_k<<<16, 256>>>(Wo,  pHWhi + 12288, pHWlo + 12288, 64, 16, 64);

    dim3 mmaG(16, 1, 16);
    for (int t = 0; t < TTi; t++) {
        for (int sub = 0; sub < 2; sub++) {
            if (t || sub)
                gemmP_hmma<<<mmaG, 256, GP3>>>(pAhi, pAlo, pA2hi, pA2lo,
                    pShi, pSlo, 128, sS, 0, pB1hi, pB1lo, pB2hi, pB2lo, 128, sS, 0);
            denseODE_k<<<dim3(128, 1, 2), 256, OD_SMEM>>>((sub == 1) ? t : -1,
                pOW0hi, pOW0lo, pOWouthi, pOWoutlo, oV_b0, oG_b0, oV_bout, oG_bout);
        }
        if (t < TTi - 1) {
            gemmP_hmma<<<mmaG, 256, GP3>>>(pAhi, pAlo, pA2hi, pA2lo,
                pShi, pSlo, 128, sS, 0, pB1hi, pB1lo, pB2hi, pB2lo, 128, sS, 0);
            denseG_k<<<dim3(128, 1, 2), 256, DG_SMEM>>>(t,
                pShi, pSlo, pGWghi, pGWglo, pGWghi + 32768, pGWglo + 32768,
                gV_bg, gG_bg);
            gemmP_hmma<<<mmaG, 256, GP3>>>(pAhi, pAlo, pA2hi, pA2lo,
                pRHhi, pRHlo, 128, sS, 0, pB1hi, pB1lo, pB2hi, pB2lo, 128, sS, 0);
            denseC_k<<<dim3(128, 1, 2), 256, DC_SMEM>>>(t,
                pRHhi, pRHlo, pGWchi, pGWclo, pGWchi + 16384, pGWclo + 16384,
                gV_bc, gG_bc);
        }
    }

    // fused output head over t = 1..39 (rows 319488 = 4992 * 64)
    headF_k<<<4992, 256, HF_SMEM>>>(bz1, bz2, bz3, bo, (float*)d_out);
}